// round 12
// baseline (speedup 1.0000x reference)
#include <cuda_runtime.h>
#include <cuda_fp16.h>

// Problem constants
#define B_  8
#define T_  1024
#define D_  1024
#define H_  16
#define DH_ 64
#define BT  (B_*T_)        // 8192
#define D3  (3*D_)         // 3072

#define KSD 40             // dense gemm smem row stride (32 + 8 pad), halves
#define LS 72              // attention smem row stride (64 + 8 pad), halves

#define STG_BYTES 20480    // one dense stage: (128+128) rows * KSD * 2 bytes
#define DG_DSMEM  (3 * STG_BYTES)   // 61440

typedef unsigned int u32;

// Scratch (__device__ globals — referenced ONLY from device code!)
static __device__ __half g_x16[(long)BT * D_];       // x fp16, 16MB
static __device__ __half g_wqkv16[(long)D3 * D_];    // W_qkv fp16, 6MB
static __device__ __half g_wproj16[(long)D_ * D_];   // W_proj fp16, 2MB
static __device__ __half g_qkv[(long)BT * D3];       // [t][3D] fp16, 48MB
static __device__ float  g_Z[(long)B_*H_*T_];        // softmax denominators
static __device__ __half g_ao[(long)BT * D_];        // [t][D] fp16, 16MB

// ---------------------------------------------------------------------------
// PTX helpers
// ---------------------------------------------------------------------------
__device__ __forceinline__ u32 smem_u32(const void* p) {
    return (u32)__cvta_generic_to_shared(p);
}
__device__ __forceinline__ void ldsm_x4(u32& r0, u32& r1, u32& r2, u32& r3, u32 a) {
    asm volatile("ldmatrix.sync.aligned.m8n8.x4.shared.b16 {%0,%1,%2,%3},[%4];"
                 : "=r"(r0), "=r"(r1), "=r"(r2), "=r"(r3) : "r"(a));
}
__device__ __forceinline__ void ldsm_x2(u32& r0, u32& r1, u32 a) {
    asm volatile("ldmatrix.sync.aligned.m8n8.x2.shared.b16 {%0,%1},[%2];"
                 : "=r"(r0), "=r"(r1) : "r"(a));
}
__device__ __forceinline__ void ldsm_x2t(u32& r0, u32& r1, u32 a) {
    asm volatile("ldmatrix.sync.aligned.m8n8.x2.trans.shared.b16 {%0,%1},[%2];"
                 : "=r"(r0), "=r"(r1) : "r"(a));
}
__device__ __forceinline__ void mma16816(float c[4],
                                         u32 a0, u32 a1, u32 a2, u32 a3,
                                         u32 b0, u32 b1) {
    asm volatile("mma.sync.aligned.m16n8k16.row.col.f32.f16.f16.f32 "
                 "{%0,%1,%2,%3},{%4,%5,%6,%7},{%8,%9},{%0,%1,%2,%3};"
                 : "+f"(c[0]), "+f"(c[1]), "+f"(c[2]), "+f"(c[3])
                 : "r"(a0), "r"(a1), "r"(a2), "r"(a3), "r"(b0), "r"(b1));
}
__device__ __forceinline__ void cpa16(u32 dst, const void* src) {
    asm volatile("cp.async.cg.shared.global [%0],[%1],16;" :: "r"(dst), "l"(src));
}
#define CP_COMMIT() asm volatile("cp.async.commit_group;")
#define CP_WAIT0()  asm volatile("cp.async.wait_group 0;")
#define CP_WAIT1()  asm volatile("cp.async.wait_group 1;")

// ---------------------------------------------------------------------------
// fp32 -> fp16 conversion (globals named in device code only)
// ---------------------------------------------------------------------------
__device__ __forceinline__ void f2h_body(const float* __restrict__ s, __half* __restrict__ d)
{
    long i = ((long)blockIdx.x * blockDim.x + threadIdx.x) * 8;
    float4 v0 = *(const float4*)(s + i);
    float4 v1 = *(const float4*)(s + i + 4);
    uint4 o;
    __half2* hp = (__half2*)&o;
    hp[0] = __floats2half2_rn(v0.x, v0.y);
    hp[1] = __floats2half2_rn(v0.z, v0.w);
    hp[2] = __floats2half2_rn(v1.x, v1.y);
    hp[3] = __floats2half2_rn(v1.z, v1.w);
    *(uint4*)(d + i) = o;
}
__global__ void k_f2h_x(const float* __restrict__ s)     { f2h_body(s, g_x16); }
__global__ void k_f2h_wqkv(const float* __restrict__ s)  { f2h_body(s, g_wqkv16); }
__global__ void k_f2h_wproj(const float* __restrict__ s) { f2h_body(s, g_wproj16); }

// ---------------------------------------------------------------------------
// Dense NT GEMM body: C[m,n] = sum_k A[m][k]*B[n][k]
// Tile 128x128x32, 256 threads = 8 warps (2 x 4), warp tile 64x32.
// 3-stage cp.async pipeline (dynamic smem), x4 fragments for A and B.
// ---------------------------------------------------------------------------
template<bool CF32>
__device__ __forceinline__ void gemm128_body(
    const __half* __restrict__ A, const __half* __restrict__ B, void* Cp,
    int K, long ldc)
{
    extern __shared__ __align__(16) char dsm[];
    const u32 s0 = smem_u32(dsm);

    const int t = threadIdx.x;
    const int warp = t >> 5, lane = t & 31;
    const int wm = warp >> 2, wn = warp & 3;
    const long m0 = (long)blockIdx.y * 128, n0 = (long)blockIdx.x * 128;

    const int lr = t >> 2;          // 0..63
    const int lc = (t & 3) * 8;     // 0,8,16,24 halves

    const __half* Ag0 = A + (m0 + lr) * (long)K + lc;
    const __half* Ag1 = Ag0 + 64 * (long)K;
    const __half* Bg0 = B + (n0 + lr) * (long)K + lc;
    const __half* Bg1 = Bg0 + 64 * (long)K;

    // Per-stage smem write offsets (bytes, relative to stage base)
    const u32 oA0 = (u32)((lr * KSD + lc) * 2);
    const u32 oA1 = (u32)(((lr + 64) * KSD + lc) * 2);
    const u32 oB0 = (u32)(10240 + (lr * KSD + lc) * 2);
    const u32 oB1 = (u32)(10240 + ((lr + 64) * KSD + lc) * 2);

    const int KT = K >> 5;

    // Prologue: stages 0 and 1
    {
        cpa16(s0 + oA0, Ag0); cpa16(s0 + oA1, Ag1);
        cpa16(s0 + oB0, Bg0); cpa16(s0 + oB1, Bg1);
        CP_COMMIT();
        const u32 sb = s0 + STG_BYTES;
        cpa16(sb + oA0, Ag0 + 32); cpa16(sb + oA1, Ag1 + 32);
        cpa16(sb + oB0, Bg0 + 32); cpa16(sb + oB1, Bg1 + 32);
        CP_COMMIT();
    }

    float acc[4][4][4];
#pragma unroll
    for (int i = 0; i < 4; ++i)
#pragma unroll
        for (int j = 0; j < 4; ++j)
#pragma unroll
            for (int k = 0; k < 4; ++k) acc[i][j][k] = 0.0f;

    // Fragment base offsets (bytes, relative to stage base)
    const u32 aoff = (u32)(((wm * 64 + (lane & 15)) * KSD + (lane >> 4) * 8) * 2);
    const u32 boff = (u32)(10240 + ((wn * 32 + (lane & 15)) * KSD + (lane >> 4) * 8) * 2);

    int st = 0;
    for (int kt = 0; kt < KT; ++kt) {
        CP_WAIT1();            // stage kt ready (≤1 group may stay in flight)
        __syncthreads();

        // Issue stage kt+2 (overwrites stage used in iter kt-1, safe after sync)
        if (kt + 2 < KT) {
            int s2 = st + 2; if (s2 >= 3) s2 -= 3;
            const u32 sb = s0 + (u32)s2 * STG_BYTES;
            const long ko = (long)(kt + 2) * 32;
            cpa16(sb + oA0, Ag0 + ko); cpa16(sb + oA1, Ag1 + ko);
            cpa16(sb + oB0, Bg0 + ko); cpa16(sb + oB1, Bg1 + ko);
        }
        CP_COMMIT();

        const u32 base = s0 + (u32)st * STG_BYTES;
        const u32 ab = base + aoff;
        const u32 bb = base + boff;
#pragma unroll
        for (int ks = 0; ks < 2; ++ks) {
            u32 a[4][4], b[2][4];
#pragma unroll
            for (int mi = 0; mi < 4; ++mi)
                ldsm_x4(a[mi][0], a[mi][1], a[mi][2], a[mi][3],
                        ab + (u32)((mi * 16 * KSD + ks * 16) * 2));
#pragma unroll
            for (int nj = 0; nj < 2; ++nj)
                ldsm_x4(b[nj][0], b[nj][1], b[nj][2], b[nj][3],
                        bb + (u32)((nj * 16 * KSD + ks * 16) * 2));
#pragma unroll
            for (int mi = 0; mi < 4; ++mi) {
#pragma unroll
                for (int ni = 0; ni < 4; ++ni) {
                    const int nj = ni >> 1;
                    u32 b0 = (ni & 1) ? b[nj][1] : b[nj][0];
                    u32 b1 = (ni & 1) ? b[nj][3] : b[nj][2];
                    mma16816(acc[mi][ni], a[mi][0], a[mi][1], a[mi][2], a[mi][3], b0, b1);
                }
            }
        }
        if (++st == 3) st = 0;
    }

    const int g = lane >> 2, tq = lane & 3;
#pragma unroll
    for (int mi = 0; mi < 4; ++mi) {
#pragma unroll
        for (int ni = 0; ni < 4; ++ni) {
            long row = m0 + wm * 64 + mi * 16 + g;
            long col = n0 + wn * 32 + ni * 8 + tq * 2;
            if (CF32) {
                float* C = (float*)Cp;
                *(float2*)(C + row * ldc + col)       = make_float2(acc[mi][ni][0], acc[mi][ni][1]);
                *(float2*)(C + (row + 8) * ldc + col) = make_float2(acc[mi][ni][2], acc[mi][ni][3]);
            } else {
                __half* C = (__half*)Cp;
                *(__half2*)(C + row * ldc + col)       = __floats2half2_rn(acc[mi][ni][0], acc[mi][ni][1]);
                *(__half2*)(C + (row + 8) * ldc + col) = __floats2half2_rn(acc[mi][ni][2], acc[mi][ni][3]);
            }
        }
    }
}

__global__ void __launch_bounds__(256, 2) k_qkv16()
{
    gemm128_body<false>(g_x16, g_wqkv16, g_qkv, D_, D3);
}
__global__ void __launch_bounds__(256, 2) k_proj16(float* __restrict__ out)
{
    gemm128_body<true>(g_ao, g_wproj16, out, D_, D_);
}

// ===========================================================================
// k_zsum: Z[k] = sum_q exp(scale * K[k]·Q[q])  — cp.async double-buffered Q,
// x4 B-fragments
// ===========================================================================
__global__ void k_zsum()
{
    __shared__ __align__(16) __half sK[128 * LS];
    __shared__ __align__(16) __half sQ[2][64 * LS];

    const int kc = blockIdx.x, bh = blockIdx.y;
    const int b = bh >> 4, h = bh & 15;
    const int t = threadIdx.x;
    const int warp = t >> 5, lane = t & 31;
    const int r2 = t >> 2, c2 = (t & 3) * 8;

    const __half* Qg = g_qkv + (long)b * T_ * D3 + h * DH_;
    const u32 dQ = smem_u32(&sQ[0][r2 * LS + c2]);
    const u32 QSBY = (u32)sizeof(sQ[0]);

    {
        const __half* Qsrc = Qg + (long)r2 * D3;
        cpa16(dQ, Qsrc + c2);
        cpa16(dQ + 64, Qsrc + c2 + 32);
        CP_COMMIT();
    }

    {
        const __half* Kg = g_qkv + ((long)b * T_ + kc * 128) * D3 + D_ + h * DH_;
        const int r_ = t >> 3, c_ = (t & 7) * 8;
#pragma unroll
        for (int p = 0; p < 4; ++p) {
            int r = r_ + p * 32;
            *(uint4*)&sK[r * LS + c_] = *(const uint4*)(Kg + (long)r * D3 + c_);
        }
    }
    __syncthreads();

    u32 a[4][4];
    {
        const u32 abase = smem_u32(&sK[(warp * 16 + (lane & 15)) * LS + (lane >> 4) * 8]);
#pragma unroll
        for (int ks = 0; ks < 4; ++ks)
            ldsm_x4(a[ks][0], a[ks][1], a[ks][2], a[ks][3], abase + (u32)(ks * 16 * 2));
    }

    float zacc0 = 0.0f, zacc1 = 0.0f;
    const u32 bqbase = smem_u32(&sQ[0][(lane & 15) * LS + (lane >> 4) * 8]);

    for (int qt = 0; qt < 16; ++qt) {
        const int st = qt & 1;
        CP_WAIT0();
        __syncthreads();

        if (qt + 1 < 16) {
            const __half* Qsrc = Qg + (long)((qt + 1) * 64 + r2) * D3;
            const u32 o = (u32)(st ^ 1) * QSBY;
            cpa16(dQ + o, Qsrc + c2);
            cpa16(dQ + o + 64, Qsrc + c2 + 32);
        }
        CP_COMMIT();

        float c[8][4];
#pragma unroll
        for (int ni = 0; ni < 8; ++ni)
#pragma unroll
            for (int j = 0; j < 4; ++j) c[ni][j] = 0.0f;

        const u32 bq0 = bqbase + (u32)st * QSBY;
#pragma unroll
        for (int ks = 0; ks < 4; ++ks) {
            u32 bq[4][4];
#pragma unroll
            for (int nj = 0; nj < 4; ++nj)
                ldsm_x4(bq[nj][0], bq[nj][1], bq[nj][2], bq[nj][3],
                        bq0 + (u32)((nj * 16 * LS + ks * 16) * 2));
#pragma unroll
            for (int ni = 0; ni < 8; ++ni) {
                const int nj = ni >> 1;
                u32 b0 = (ni & 1) ? bq[nj][1] : bq[nj][0];
                u32 b1 = (ni & 1) ? bq[nj][3] : bq[nj][2];
                mma16816(c[ni], a[ks][0], a[ks][1], a[ks][2], a[ks][3], b0, b1);
            }
        }

#pragma unroll
        for (int ni = 0; ni < 8; ++ni) {
            zacc0 += __expf(0.125f * c[ni][0]) + __expf(0.125f * c[ni][1]);
            zacc1 += __expf(0.125f * c[ni][2]) + __expf(0.125f * c[ni][3]);
        }
    }

    zacc0 += __shfl_xor_sync(0xffffffffu, zacc0, 1);
    zacc0 += __shfl_xor_sync(0xffffffffu, zacc0, 2);
    zacc1 += __shfl_xor_sync(0xffffffffu, zacc1, 1);
    zacc1 += __shfl_xor_sync(0xffffffffu, zacc1, 2);
    if ((lane & 3) == 0) {
        int krow = kc * 128 + warp * 16 + (lane >> 2);
        g_Z[(long)bh * T_ + krow]     = zacc0;
        g_Z[(long)bh * T_ + krow + 8] = zacc1;
    }
}

// ===========================================================================
// k_attn: out[q,d] = sum_k exp(scale*q·k)/Z[k] * V[k,d]
// cp.async double-buffered K/V; x4 K-fragments; V via ldsm_x2t (unchanged)
// ===========================================================================
__global__ void k_attn()
{
    __shared__ __align__(16) __half sP[128 * LS];
    __shared__ __align__(16) __half sK[2][64 * LS];
    __shared__ __align__(16) __half sV[2][64 * LS];
    __shared__ float sRZ[2][64];

    const int qt = blockIdx.x, bh = blockIdx.y;
    const int b = bh >> 4, h = bh & 15;
    const int t = threadIdx.x;
    const int warp = t >> 5, lane = t & 31;
    const int g = lane >> 2, tq = lane & 3;
    const int r2 = t >> 2, c2 = (t & 3) * 8;

    const __half* Kg = g_qkv + (long)b * T_ * D3 + D_ + h * DH_;
    const __half* Vg = g_qkv + (long)b * T_ * D3 + 2 * D_ + h * DH_;
    const float* Zp = g_Z + (long)bh * T_;

    const u32 dK = smem_u32(&sK[0][r2 * LS + c2]);
    const u32 dV = smem_u32(&sV[0][r2 * LS + c2]);
    const u32 CSBY = (u32)sizeof(sK[0]);

    {
        const __half* Ksrc = Kg + (long)r2 * D3;
        const __half* Vsrc = Vg + (long)r2 * D3;
        cpa16(dK, Ksrc + c2);      cpa16(dK + 64, Ksrc + c2 + 32);
        cpa16(dV, Vsrc + c2);      cpa16(dV + 64, Vsrc + c2 + 32);
        CP_COMMIT();
    }

    {
        const __half* Qg = g_qkv + ((long)b * T_ + qt * 128) * D3 + h * DH_;
        const int r_ = t >> 3, c_ = (t & 7) * 8;
#pragma unroll
        for (int p = 0; p < 4; ++p) {
            int r = r_ + p * 32;
            *(uint4*)&sP[r * LS + c_] = *(const uint4*)(Qg + (long)r * D3 + c_);
        }
    }
    __syncthreads();

    u32 aq[4][4];
    const u32 pbase = smem_u32(&sP[(warp * 16 + (lane & 15)) * LS + (lane >> 4) * 8]);
#pragma unroll
    for (int ks = 0; ks < 4; ++ks)
        ldsm_x4(aq[ks][0], aq[ks][1], aq[ks][2], aq[ks][3], pbase + (u32)(ks * 16 * 2));

    float o[8][4];
#pragma unroll
    for (int ni = 0; ni < 8; ++ni)
#pragma unroll
        for (int j = 0; j < 4; ++j) o[ni][j] = 0.0f;

    const u32 bkbase = smem_u32(&sK[0][(lane & 15) * LS + (lane >> 4) * 8]);
    const u32 bvbase = smem_u32(&sV[0][(lane & 15) * LS]);

    for (int kc = 0; kc < 16; ++kc) {
        const int st = kc & 1;
        CP_WAIT0();
        if (t < 64) sRZ[st][t] = 1.0f / Zp[kc * 64 + t];
        __syncthreads();

        if (kc + 1 < 16) {
            const __half* Ksrc = Kg + (long)((kc + 1) * 64 + r2) * D3;
            const __half* Vsrc = Vg + (long)((kc + 1) * 64 + r2) * D3;
            const u32 oo = (u32)(st ^ 1) * CSBY;
            cpa16(dK + oo, Ksrc + c2);      cpa16(dK + oo + 64, Ksrc + c2 + 32);
            cpa16(dV + oo, Vsrc + c2);      cpa16(dV + oo + 64, Vsrc + c2 + 32);
        }
        CP_COMMIT();

        float c[8][4];
#pragma unroll
        for (int ni = 0; ni < 8; ++ni)
#pragma unroll
            for (int j = 0; j < 4; ++j) c[ni][j] = 0.0f;

        const u32 bk0 = bkbase + (u32)st * CSBY;
#pragma unroll
        for (int ks = 0; ks < 4; ++ks) {
            u32 bk[4][4];
#pragma unroll
            for (int nj = 0; nj < 4; ++nj)
                ldsm_x4(bk[nj][0], bk[nj][1], bk[nj][2], bk[nj][3],
                        bk0 + (u32)((nj * 16 * LS + ks * 16) * 2));
#pragma unroll
            for (int ni = 0; ni < 8; ++ni) {
                const int nj = ni >> 1;
                u32 b0 = (ni & 1) ? bk[nj][1] : bk[nj][0];
                u32 b1 = (ni & 1) ? bk[nj][3] : bk[nj][2];
                mma16816(c[ni], aq[ks][0], aq[ks][1], aq[ks][2], aq[ks][3], b0, b1);
            }
        }

#pragma unroll
        for (int ni = 0; ni < 8; ++ni) {
            int col = ni * 8 + tq * 2;
            float rz0 = sRZ[st][col], rz1 = sRZ[st][col + 1];
            __half2 p01 = __floats2half2_rn(__expf(0.125f * c[ni][0]) * rz0,
                                            __expf(0.125f * c[ni][1]) * rz1);
            __half2 p23 = __floats2half2_rn(__expf(0.125f * c[ni][2]) * rz0,
                                            __expf(0.125f * c[ni][3]) * rz1);
            *(__half2*)&sP[(warp * 16 + g) * LS + col]     = p01;
            *(__half2*)&sP[(warp * 16 + g + 8) * LS + col] = p23;
        }
        __syncthreads();

        const u32 bv0 = bvbase + (u32)st * CSBY;
#pragma unroll
        for (int ks = 0; ks < 4; ++ks) {
            u32 ap[4];
            ldsm_x4(ap[0], ap[1], ap[2], ap[3], pbase + (u32)(ks * 16 * 2));
            u32 bv[8][2];
#pragma unroll
            for (int nd = 0; nd < 8; ++nd)
                ldsm_x2t(bv[nd][0], bv[nd][1],
                         bv0 + (u32)((ks * 16 * LS + nd * 8) * 2));
#pragma unroll
            for (int nd = 0; nd < 8; ++nd)
                mma16816(o[nd], ap[0], ap[1], ap[2], ap[3], bv[nd][0], bv[nd][1]);
        }
        __syncthreads();
    }

    __half* Og = g_ao + ((long)b * T_ + qt * 128) * D_ + h * DH_;
#pragma unroll
    for (int nd = 0; nd < 8; ++nd) {
        int row = warp * 16 + g;
        int col = nd * 8 + tq * 2;
        *(__half2*)(Og + (long)row * D_ + col)       = __floats2half2_rn(o[nd][0], o[nd][1]);
        *(__half2*)(Og + (long)(row + 8) * D_ + col) = __floats2half2_rn(o[nd][2], o[nd][3]);
    }
}

// ---------------------------------------------------------------------------
extern "C" void kernel_launch(void* const* d_in, const int* in_sizes, int n_in,
                              void* d_out, int out_size)
{
    const float* x      = (const float*)d_in[0];   // [8,1024,1024]
    const float* w_qkv  = (const float*)d_in[1];   // [3072,1024]
    const float* w_proj = (const float*)d_in[2];   // [1024,1024]
    float* out = (float*)d_out;                    // [8,1024,1024]

    cudaFuncSetAttribute(k_qkv16,  cudaFuncAttributeMaxDynamicSharedMemorySize, DG_DSMEM);
    cudaFuncSetAttribute(k_proj16, cudaFuncAttributeMaxDynamicSharedMemorySize, DG_DSMEM);

    k_f2h_x    <<<(long)BT * D_ / 2048, 256>>>(x);
    k_f2h_wqkv <<<(long)D3 * D_ / 2048, 256>>>(w_qkv);
    k_f2h_wproj<<<(long)D_ * D_ / 2048, 256>>>(w_proj);

    k_qkv16 <<<dim3(D3 / 128, BT / 128), 256, DG_DSMEM>>>();
    k_zsum  <<<dim3(T_ / 128, B_ * H_), 256>>>();
    k_attn  <<<dim3(T_ / 128, B_ * H_), 256>>>();
    k_proj16<<<dim3(D_ / 128, BT / 128), 256, DG_DSMEM>>>(out);
}

// round 13
// speedup vs baseline: 1.0327x; 1.0327x over previous
#include <cuda_runtime.h>
#include <cuda_fp16.h>

// Problem constants
#define B_  8
#define T_  1024
#define D_  1024
#define H_  16
#define DH_ 64
#define BT  (B_*T_)        // 8192
#define D3  (3*D_)         // 3072

#define KSD 40             // dense gemm smem row stride (32 + 8 pad), halves
#define LS 72              // attention smem row stride (64 + 8 pad), halves

#define STG_BYTES 20480u   // one dense stage: (128+128) rows * KSD * 2 bytes
#define DG_DSMEM  (4 * 20480)   // 81920, 4-stage

typedef unsigned int u32;

// Scratch (__device__ globals — referenced ONLY from device code!)
static __device__ __half g_x16[(long)BT * D_];       // x fp16, 16MB
static __device__ __half g_wqkv16[(long)D3 * D_];    // W_qkv fp16, 6MB
static __device__ __half g_wproj16[(long)D_ * D_];   // W_proj fp16, 2MB
static __device__ __half g_qkv[(long)BT * D3];       // [t][3D] fp16, 48MB
static __device__ float  g_Z[(long)B_*H_*T_];        // softmax denominators
static __device__ __half g_ao[(long)BT * D_];        // [t][D] fp16, 16MB

// ---------------------------------------------------------------------------
// PTX helpers
// ---------------------------------------------------------------------------
__device__ __forceinline__ u32 smem_u32(const void* p) {
    return (u32)__cvta_generic_to_shared(p);
}
__device__ __forceinline__ void ldsm_x4(u32& r0, u32& r1, u32& r2, u32& r3, u32 a) {
    asm volatile("ldmatrix.sync.aligned.m8n8.x4.shared.b16 {%0,%1,%2,%3},[%4];"
                 : "=r"(r0), "=r"(r1), "=r"(r2), "=r"(r3) : "r"(a));
}
__device__ __forceinline__ void ldsm_x2(u32& r0, u32& r1, u32 a) {
    asm volatile("ldmatrix.sync.aligned.m8n8.x2.shared.b16 {%0,%1},[%2];"
                 : "=r"(r0), "=r"(r1) : "r"(a));
}
__device__ __forceinline__ void ldsm_x2t(u32& r0, u32& r1, u32 a) {
    asm volatile("ldmatrix.sync.aligned.m8n8.x2.trans.shared.b16 {%0,%1},[%2];"
                 : "=r"(r0), "=r"(r1) : "r"(a));
}
__device__ __forceinline__ void mma16816(float c[4],
                                         u32 a0, u32 a1, u32 a2, u32 a3,
                                         u32 b0, u32 b1) {
    asm volatile("mma.sync.aligned.m16n8k16.row.col.f32.f16.f16.f32 "
                 "{%0,%1,%2,%3},{%4,%5,%6,%7},{%8,%9},{%0,%1,%2,%3};"
                 : "+f"(c[0]), "+f"(c[1]), "+f"(c[2]), "+f"(c[3])
                 : "r"(a0), "r"(a1), "r"(a2), "r"(a3), "r"(b0), "r"(b1));
}
__device__ __forceinline__ void cpa16(u32 dst, const void* src) {
    asm volatile("cp.async.cg.shared.global [%0],[%1],16;" :: "r"(dst), "l"(src));
}
#define CP_COMMIT() asm volatile("cp.async.commit_group;")
#define CP_WAIT0()  asm volatile("cp.async.wait_group 0;")
#define CP_WAIT2()  asm volatile("cp.async.wait_group 2;")

// ---------------------------------------------------------------------------
// fp32 -> fp16 conversion (globals named in device code only)
// ---------------------------------------------------------------------------
__device__ __forceinline__ void f2h_body(const float* __restrict__ s, __half* __restrict__ d)
{
    long i = ((long)blockIdx.x * blockDim.x + threadIdx.x) * 8;
    float4 v0 = *(const float4*)(s + i);
    float4 v1 = *(const float4*)(s + i + 4);
    uint4 o;
    __half2* hp = (__half2*)&o;
    hp[0] = __floats2half2_rn(v0.x, v0.y);
    hp[1] = __floats2half2_rn(v0.z, v0.w);
    hp[2] = __floats2half2_rn(v1.x, v1.y);
    hp[3] = __floats2half2_rn(v1.z, v1.w);
    *(uint4*)(d + i) = o;
}
__global__ void k_f2h_x(const float* __restrict__ s)     { f2h_body(s, g_x16); }
__global__ void k_f2h_wqkv(const float* __restrict__ s)  { f2h_body(s, g_wqkv16); }
__global__ void k_f2h_wproj(const float* __restrict__ s) { f2h_body(s, g_wproj16); }

// ---------------------------------------------------------------------------
// Dense NT GEMM body: C[m,n] = sum_k A[m][k]*B[n][k]
// Tile 128x128x32, 256 threads = 8 warps (2 x 4), warp tile 64x32.
// 4-stage cp.async pipeline (stage = kt & 3), R9-proven fragment scheme.
// ---------------------------------------------------------------------------
template<bool CF32>
__device__ __forceinline__ void gemm128_body(
    const __half* __restrict__ A, const __half* __restrict__ B, void* Cp,
    int K, long ldc)
{
    extern __shared__ __align__(16) char dsm[];
    const u32 s0 = smem_u32(dsm);

    const int t = threadIdx.x;
    const int warp = t >> 5, lane = t & 31;
    const int wm = warp >> 2, wn = warp & 3;
    const long m0 = (long)blockIdx.y * 128, n0 = (long)blockIdx.x * 128;

    const int lr = t >> 2;          // 0..63
    const int lc = (t & 3) * 8;     // 0,8,16,24 halves

    const __half* Ag0 = A + (m0 + lr) * (long)K + lc;
    const __half* Ag1 = Ag0 + 64 * (long)K;
    const __half* Bg0 = B + (n0 + lr) * (long)K + lc;
    const __half* Bg1 = Bg0 + 64 * (long)K;

    // Per-stage smem write offsets (bytes, relative to stage base)
    const u32 oA0 = (u32)((lr * KSD + lc) * 2);
    const u32 oA1 = (u32)(((lr + 64) * KSD + lc) * 2);
    const u32 oB0 = (u32)(10240 + (lr * KSD + lc) * 2);
    const u32 oB1 = (u32)(10240 + ((lr + 64) * KSD + lc) * 2);

    const int KT = K >> 5;

    // Prologue: issue tiles 0,1,2 into stages 0,1,2
#pragma unroll
    for (int p = 0; p < 3; ++p) {
        const u32 sb = s0 + (u32)p * STG_BYTES;
        cpa16(sb + oA0, Ag0 + p * 32); cpa16(sb + oA1, Ag1 + p * 32);
        cpa16(sb + oB0, Bg0 + p * 32); cpa16(sb + oB1, Bg1 + p * 32);
        CP_COMMIT();
    }

    float acc[4][4][4];
#pragma unroll
    for (int i = 0; i < 4; ++i)
#pragma unroll
        for (int j = 0; j < 4; ++j)
#pragma unroll
            for (int k = 0; k < 4; ++k) acc[i][j][k] = 0.0f;

    // Fragment base offsets (bytes, relative to stage base) — R9-proven scheme
    const u32 aoff = (u32)(((wm * 64 + (lane & 15)) * KSD + (lane >> 4) * 8) * 2);
    const u32 boff = (u32)(10240 + ((wn * 32 + (lane & 7)) * KSD + ((lane >> 3) & 1) * 8) * 2);

    for (int kt = 0; kt < KT; ++kt) {
        CP_WAIT2();            // tile kt landed (≤2 newer groups still in flight)
        __syncthreads();

        // Issue tile kt+3 into stage (kt+3)&3 == (kt-1)&3 (read finished last iter)
        if (kt + 3 < KT) {
            const u32 sb = s0 + (u32)((kt + 3) & 3) * STG_BYTES;
            const long ko = (long)(kt + 3) * 32;
            cpa16(sb + oA0, Ag0 + ko); cpa16(sb + oA1, Ag1 + ko);
            cpa16(sb + oB0, Bg0 + ko); cpa16(sb + oB1, Bg1 + ko);
        }
        CP_COMMIT();

        const u32 base = s0 + (u32)(kt & 3) * STG_BYTES;
        const u32 ab = base + aoff;
        const u32 bb = base + boff;
#pragma unroll
        for (int ks = 0; ks < 2; ++ks) {
            u32 a[4][4], b[4][2];
#pragma unroll
            for (int mi = 0; mi < 4; ++mi)
                ldsm_x4(a[mi][0], a[mi][1], a[mi][2], a[mi][3],
                        ab + (u32)((mi * 16 * KSD + ks * 16) * 2));
#pragma unroll
            for (int ni = 0; ni < 4; ++ni)
                ldsm_x2(b[ni][0], b[ni][1],
                        bb + (u32)((ni * 8 * KSD + ks * 16) * 2));
#pragma unroll
            for (int mi = 0; mi < 4; ++mi)
#pragma unroll
                for (int ni = 0; ni < 4; ++ni)
                    mma16816(acc[mi][ni], a[mi][0], a[mi][1], a[mi][2], a[mi][3],
                             b[ni][0], b[ni][1]);
        }
    }

    const int g = lane >> 2, tq = lane & 3;
#pragma unroll
    for (int mi = 0; mi < 4; ++mi) {
#pragma unroll
        for (int ni = 0; ni < 4; ++ni) {
            long row = m0 + wm * 64 + mi * 16 + g;
            long col = n0 + wn * 32 + ni * 8 + tq * 2;
            if (CF32) {
                float* C = (float*)Cp;
                *(float2*)(C + row * ldc + col)       = make_float2(acc[mi][ni][0], acc[mi][ni][1]);
                *(float2*)(C + (row + 8) * ldc + col) = make_float2(acc[mi][ni][2], acc[mi][ni][3]);
            } else {
                __half* C = (__half*)Cp;
                *(__half2*)(C + row * ldc + col)       = __floats2half2_rn(acc[mi][ni][0], acc[mi][ni][1]);
                *(__half2*)(C + (row + 8) * ldc + col) = __floats2half2_rn(acc[mi][ni][2], acc[mi][ni][3]);
            }
        }
    }
}

__global__ void __launch_bounds__(256, 2) k_qkv16()
{
    gemm128_body<false>(g_x16, g_wqkv16, g_qkv, D_, D3);
}
__global__ void __launch_bounds__(256, 2) k_proj16(float* __restrict__ out)
{
    gemm128_body<true>(g_ao, g_wproj16, out, D_, D_);
}

// ===========================================================================
// k_zsum: Z[k] = sum_q exp(scale * K[k]·Q[q])  — [R9 verbatim]
// ===========================================================================
__global__ void k_zsum()
{
    __shared__ __align__(16) __half sK[128 * LS];
    __shared__ __align__(16) __half sQ[2][64 * LS];

    const int kc = blockIdx.x, bh = blockIdx.y;
    const int b = bh >> 4, h = bh & 15;
    const int t = threadIdx.x;
    const int warp = t >> 5, lane = t & 31;
    const int r2 = t >> 2, c2 = (t & 3) * 8;

    const __half* Qg = g_qkv + (long)b * T_ * D3 + h * DH_;
    const u32 dQ = smem_u32(&sQ[0][r2 * LS + c2]);
    const u32 QSBY = (u32)sizeof(sQ[0]);

    {
        const __half* Qsrc = Qg + (long)r2 * D3;
        cpa16(dQ, Qsrc + c2);
        cpa16(dQ + 64, Qsrc + c2 + 32);
        CP_COMMIT();
    }

    {
        const __half* Kg = g_qkv + ((long)b * T_ + kc * 128) * D3 + D_ + h * DH_;
        const int r_ = t >> 3, c_ = (t & 7) * 8;
#pragma unroll
        for (int p = 0; p < 4; ++p) {
            int r = r_ + p * 32;
            *(uint4*)&sK[r * LS + c_] = *(const uint4*)(Kg + (long)r * D3 + c_);
        }
    }
    __syncthreads();

    u32 a[4][4];
    {
        const u32 abase = smem_u32(&sK[(warp * 16 + (lane & 15)) * LS + (lane >> 4) * 8]);
#pragma unroll
        for (int ks = 0; ks < 4; ++ks)
            ldsm_x4(a[ks][0], a[ks][1], a[ks][2], a[ks][3], abase + (u32)(ks * 16 * 2));
    }

    float zacc0 = 0.0f, zacc1 = 0.0f;
    const u32 bqbase = smem_u32(&sQ[0][(lane & 7) * LS + ((lane >> 3) & 1) * 8]);

    for (int qt = 0; qt < 16; ++qt) {
        const int st = qt & 1;
        CP_WAIT0();
        __syncthreads();

        if (qt + 1 < 16) {
            const __half* Qsrc = Qg + (long)((qt + 1) * 64 + r2) * D3;
            const u32 o = (u32)(st ^ 1) * QSBY;
            cpa16(dQ + o, Qsrc + c2);
            cpa16(dQ + o + 64, Qsrc + c2 + 32);
        }
        CP_COMMIT();

        float c[8][4];
#pragma unroll
        for (int ni = 0; ni < 8; ++ni)
#pragma unroll
            for (int j = 0; j < 4; ++j) c[ni][j] = 0.0f;

        const u32 bq0 = bqbase + (u32)st * QSBY;
#pragma unroll
        for (int ks = 0; ks < 4; ++ks) {
            u32 bq[8][2];
#pragma unroll
            for (int ni = 0; ni < 8; ++ni)
                ldsm_x2(bq[ni][0], bq[ni][1],
                        bq0 + (u32)((ni * 8 * LS + ks * 16) * 2));
#pragma unroll
            for (int ni = 0; ni < 8; ++ni)
                mma16816(c[ni], a[ks][0], a[ks][1], a[ks][2], a[ks][3],
                         bq[ni][0], bq[ni][1]);
        }

#pragma unroll
        for (int ni = 0; ni < 8; ++ni) {
            zacc0 += __expf(0.125f * c[ni][0]) + __expf(0.125f * c[ni][1]);
            zacc1 += __expf(0.125f * c[ni][2]) + __expf(0.125f * c[ni][3]);
        }
    }

    zacc0 += __shfl_xor_sync(0xffffffffu, zacc0, 1);
    zacc0 += __shfl_xor_sync(0xffffffffu, zacc0, 2);
    zacc1 += __shfl_xor_sync(0xffffffffu, zacc1, 1);
    zacc1 += __shfl_xor_sync(0xffffffffu, zacc1, 2);
    if ((lane & 3) == 0) {
        int krow = kc * 128 + warp * 16 + (lane >> 2);
        g_Z[(long)bh * T_ + krow]     = zacc0;
        g_Z[(long)bh * T_ + krow + 8] = zacc1;
    }
}

// ===========================================================================
// k_attn: out[q,d] = sum_k exp(scale*q·k)/Z[k] * V[k,d]   [R9 verbatim]
// ===========================================================================
__global__ void k_attn()
{
    __shared__ __align__(16) __half sP[128 * LS];
    __shared__ __align__(16) __half sK[2][64 * LS];
    __shared__ __align__(16) __half sV[2][64 * LS];
    __shared__ float sRZ[2][64];

    const int qt = blockIdx.x, bh = blockIdx.y;
    const int b = bh >> 4, h = bh & 15;
    const int t = threadIdx.x;
    const int warp = t >> 5, lane = t & 31;
    const int g = lane >> 2, tq = lane & 3;
    const int r2 = t >> 2, c2 = (t & 3) * 8;

    const __half* Kg = g_qkv + (long)b * T_ * D3 + D_ + h * DH_;
    const __half* Vg = g_qkv + (long)b * T_ * D3 + 2 * D_ + h * DH_;
    const float* Zp = g_Z + (long)bh * T_;

    const u32 dK = smem_u32(&sK[0][r2 * LS + c2]);
    const u32 dV = smem_u32(&sV[0][r2 * LS + c2]);
    const u32 CSBY = (u32)sizeof(sK[0]);

    {
        const __half* Ksrc = Kg + (long)r2 * D3;
        const __half* Vsrc = Vg + (long)r2 * D3;
        cpa16(dK, Ksrc + c2);      cpa16(dK + 64, Ksrc + c2 + 32);
        cpa16(dV, Vsrc + c2);      cpa16(dV + 64, Vsrc + c2 + 32);
        CP_COMMIT();
    }

    {
        const __half* Qg = g_qkv + ((long)b * T_ + qt * 128) * D3 + h * DH_;
        const int r_ = t >> 3, c_ = (t & 7) * 8;
#pragma unroll
        for (int p = 0; p < 4; ++p) {
            int r = r_ + p * 32;
            *(uint4*)&sP[r * LS + c_] = *(const uint4*)(Qg + (long)r * D3 + c_);
        }
    }
    __syncthreads();

    u32 aq[4][4];
    const u32 pbase = smem_u32(&sP[(warp * 16 + (lane & 15)) * LS + (lane >> 4) * 8]);
#pragma unroll
    for (int ks = 0; ks < 4; ++ks)
        ldsm_x4(aq[ks][0], aq[ks][1], aq[ks][2], aq[ks][3], pbase + (u32)(ks * 16 * 2));

    float o[8][4];
#pragma unroll
    for (int ni = 0; ni < 8; ++ni)
#pragma unroll
        for (int j = 0; j < 4; ++j) o[ni][j] = 0.0f;

    const u32 bkbase = smem_u32(&sK[0][(lane & 7) * LS + ((lane >> 3) & 1) * 8]);
    const u32 bvbase = smem_u32(&sV[0][(lane & 15) * LS]);

    for (int kc = 0; kc < 16; ++kc) {
        const int st = kc & 1;
        CP_WAIT0();
        if (t < 64) sRZ[st][t] = 1.0f / Zp[kc * 64 + t];
        __syncthreads();

        if (kc + 1 < 16) {
            const __half* Ksrc = Kg + (long)((kc + 1) * 64 + r2) * D3;
            const __half* Vsrc = Vg + (long)((kc + 1) * 64 + r2) * D3;
            const u32 oo = (u32)(st ^ 1) * CSBY;
            cpa16(dK + oo, Ksrc + c2);      cpa16(dK + oo + 64, Ksrc + c2 + 32);
            cpa16(dV + oo, Vsrc + c2);      cpa16(dV + oo + 64, Vsrc + c2 + 32);
        }
        CP_COMMIT();

        float c[8][4];
#pragma unroll
        for (int ni = 0; ni < 8; ++ni)
#pragma unroll
            for (int j = 0; j < 4; ++j) c[ni][j] = 0.0f;

        const u32 bk0 = bkbase + (u32)st * CSBY;
#pragma unroll
        for (int ks = 0; ks < 4; ++ks) {
            u32 bk[8][2];
#pragma unroll
            for (int ni = 0; ni < 8; ++ni)
                ldsm_x2(bk[ni][0], bk[ni][1],
                        bk0 + (u32)((ni * 8 * LS + ks * 16) * 2));
#pragma unroll
            for (int ni = 0; ni < 8; ++ni)
                mma16816(c[ni], aq[ks][0], aq[ks][1], aq[ks][2], aq[ks][3],
                         bk[ni][0], bk[ni][1]);
        }

#pragma unroll
        for (int ni = 0; ni < 8; ++ni) {
            int col = ni * 8 + tq * 2;
            float rz0 = sRZ[st][col], rz1 = sRZ[st][col + 1];
            __half2 p01 = __floats2half2_rn(__expf(0.125f * c[ni][0]) * rz0,
                                            __expf(0.125f * c[ni][1]) * rz1);
            __half2 p23 = __floats2half2_rn(__expf(0.125f * c[ni][2]) * rz0,
                                            __expf(0.125f * c[ni][3]) * rz1);
            *(__half2*)&sP[(warp * 16 + g) * LS + col]     = p01;
            *(__half2*)&sP[(warp * 16 + g + 8) * LS + col] = p23;
        }
        __syncthreads();

        const u32 bv0 = bvbase + (u32)st * CSBY;
#pragma unroll
        for (int ks = 0; ks < 4; ++ks) {
            u32 ap[4];
            ldsm_x4(ap[0], ap[1], ap[2], ap[3], pbase + (u32)(ks * 16 * 2));
            u32 bv[8][2];
#pragma unroll
            for (int nd = 0; nd < 8; ++nd)
                ldsm_x2t(bv[nd][0], bv[nd][1],
                         bv0 + (u32)((ks * 16 * LS + nd * 8) * 2));
#pragma unroll
            for (int nd = 0; nd < 8; ++nd)
                mma16816(o[nd], ap[0], ap[1], ap[2], ap[3], bv[nd][0], bv[nd][1]);
        }
        __syncthreads();
    }

    __half* Og = g_ao + ((long)b * T_ + qt * 128) * D_ + h * DH_;
#pragma unroll
    for (int nd = 0; nd < 8; ++nd) {
        int row = warp * 16 + g;
        int col = nd * 8 + tq * 2;
        *(__half2*)(Og + (long)row * D_ + col)       = __floats2half2_rn(o[nd][0], o[nd][1]);
        *(__half2*)(Og + (long)(row + 8) * D_ + col) = __floats2half2_rn(o[nd][2], o[nd][3]);
    }
}

// ---------------------------------------------------------------------------
extern "C" void kernel_launch(void* const* d_in, const int* in_sizes, int n_in,
                              void* d_out, int out_size)
{
    const float* x      = (const float*)d_in[0];   // [8,1024,1024]
    const float* w_qkv  = (const float*)d_in[1];   // [3072,1024]
    const float* w_proj = (const float*)d_in[2];   // [1024,1024]
    float* out = (float*)d_out;                    // [8,1024,1024]

    cudaFuncSetAttribute(k_qkv16,  cudaFuncAttributeMaxDynamicSharedMemorySize, DG_DSMEM);
    cudaFuncSetAttribute(k_proj16, cudaFuncAttributeMaxDynamicSharedMemorySize, DG_DSMEM);

    k_f2h_x    <<<(long)BT * D_ / 2048, 256>>>(x);
    k_f2h_wqkv <<<(long)D3 * D_ / 2048, 256>>>(w_qkv);
    k_f2h_wproj<<<(long)D_ * D_ / 2048, 256>>>(w_proj);

    k_qkv16 <<<dim3(D3 / 128, BT / 128), 256, DG_DSMEM>>>();
    k_zsum  <<<dim3(T_ / 128, B_ * H_), 256>>>();
    k_attn  <<<dim3(T_ / 128, B_ * H_), 256>>>();
    k_proj16<<<dim3(D_ / 128, BT / 128), 256, DG_DSMEM>>>(out);
}

// round 14
// speedup vs baseline: 1.1103x; 1.0751x over previous
#include <cuda_runtime.h>
#include <cuda_fp16.h>

// Problem constants
#define B_  8
#define T_  1024
#define D_  1024
#define H_  16
#define DH_ 64
#define BT  (B_*T_)        // 8192
#define D3  (3*D_)         // 3072

#define KS2 72             // dense gemm smem row stride (64 + 8 pad), halves
#define LS 72              // attention smem row stride (64 + 8 pad), halves

#define DG_STG (256 * KS2 * 2)      // 36864 bytes: one stage (128 A rows + 128 B rows)
#define DG_DSMEM (2 * DG_STG)       // 73728, 2-stage

typedef unsigned int u32;

// Scratch (__device__ globals — referenced ONLY from device code!)
static __device__ __half g_x16[(long)BT * D_];       // x fp16, 16MB
static __device__ __half g_wqkv16[(long)D3 * D_];    // W_qkv fp16, 6MB
static __device__ __half g_wproj16[(long)D_ * D_];   // W_proj fp16, 2MB
static __device__ __half g_qkv[(long)BT * D3];       // [t][3D] fp16, 48MB
static __device__ float  g_Z[(long)B_*H_*T_];        // softmax denominators
static __device__ __half g_ao[(long)BT * D_];        // [t][D] fp16, 16MB

// ---------------------------------------------------------------------------
// PTX helpers
// ---------------------------------------------------------------------------
__device__ __forceinline__ u32 smem_u32(const void* p) {
    return (u32)__cvta_generic_to_shared(p);
}
__device__ __forceinline__ void ldsm_x4(u32& r0, u32& r1, u32& r2, u32& r3, u32 a) {
    asm volatile("ldmatrix.sync.aligned.m8n8.x4.shared.b16 {%0,%1,%2,%3},[%4];"
                 : "=r"(r0), "=r"(r1), "=r"(r2), "=r"(r3) : "r"(a));
}
__device__ __forceinline__ void ldsm_x2(u32& r0, u32& r1, u32 a) {
    asm volatile("ldmatrix.sync.aligned.m8n8.x2.shared.b16 {%0,%1},[%2];"
                 : "=r"(r0), "=r"(r1) : "r"(a));
}
__device__ __forceinline__ void ldsm_x2t(u32& r0, u32& r1, u32 a) {
    asm volatile("ldmatrix.sync.aligned.m8n8.x2.trans.shared.b16 {%0,%1},[%2];"
                 : "=r"(r0), "=r"(r1) : "r"(a));
}
__device__ __forceinline__ void mma16816(float c[4],
                                         u32 a0, u32 a1, u32 a2, u32 a3,
                                         u32 b0, u32 b1) {
    asm volatile("mma.sync.aligned.m16n8k16.row.col.f32.f16.f16.f32 "
                 "{%0,%1,%2,%3},{%4,%5,%6,%7},{%8,%9},{%0,%1,%2,%3};"
                 : "+f"(c[0]), "+f"(c[1]), "+f"(c[2]), "+f"(c[3])
                 : "r"(a0), "r"(a1), "r"(a2), "r"(a3), "r"(b0), "r"(b1));
}
__device__ __forceinline__ void cpa16(u32 dst, const void* src) {
    asm volatile("cp.async.cg.shared.global [%0],[%1],16;" :: "r"(dst), "l"(src));
}
#define CP_COMMIT() asm volatile("cp.async.commit_group;")
#define CP_WAIT0()  asm volatile("cp.async.wait_group 0;")

// ---------------------------------------------------------------------------
// fp32 -> fp16 conversion (globals named in device code only)
// ---------------------------------------------------------------------------
__device__ __forceinline__ void f2h_body(const float* __restrict__ s, __half* __restrict__ d)
{
    long i = ((long)blockIdx.x * blockDim.x + threadIdx.x) * 8;
    float4 v0 = *(const float4*)(s + i);
    float4 v1 = *(const float4*)(s + i + 4);
    uint4 o;
    __half2* hp = (__half2*)&o;
    hp[0] = __floats2half2_rn(v0.x, v0.y);
    hp[1] = __floats2half2_rn(v0.z, v0.w);
    hp[2] = __floats2half2_rn(v1.x, v1.y);
    hp[3] = __floats2half2_rn(v1.z, v1.w);
    *(uint4*)(d + i) = o;
}
__global__ void k_f2h_x(const float* __restrict__ s)     { f2h_body(s, g_x16); }
__global__ void k_f2h_wqkv(const float* __restrict__ s)  { f2h_body(s, g_wqkv16); }
__global__ void k_f2h_wproj(const float* __restrict__ s) { f2h_body(s, g_wproj16); }

// ---------------------------------------------------------------------------
// Dense NT GEMM body: C[m,n] = sum_k A[m][k]*B[n][k]
// Tile 128x128x64, 256 threads = 8 warps (2 x 4), warp tile 64x32.
// 2-stage cp.async; 16 K-iterations (halved barrier count vs BK=32).
// ---------------------------------------------------------------------------
template<bool CF32>
__device__ __forceinline__ void gemm128_body(
    const __half* __restrict__ A, const __half* __restrict__ B, void* Cp,
    int K, long ldc)
{
    extern __shared__ __align__(16) char dsm[];
    const u32 s0 = smem_u32(dsm);

    const int t = threadIdx.x;
    const int warp = t >> 5, lane = t & 31;
    const int wm = warp >> 2, wn = warp & 3;
    const long m0 = (long)blockIdx.y * 128, n0 = (long)blockIdx.x * 128;

    const int lr = t >> 3;          // 0..31 (row within 32-row pass)
    const int lc = (t & 7) * 8;     // 0..56 halves (16B chunks)

    const __half* Ag = A + (m0 + lr) * (long)K + lc;
    const __half* Bg = B + (n0 + lr) * (long)K + lc;

    // smem byte offsets within a stage: A rows [0,128), B rows [128,256)
    const u32 oBase = (u32)((lr * KS2 + lc) * 2);
    const u32 rowStep = (u32)(32 * KS2 * 2);       // 32 rows
    const u32 bHalf = (u32)(128 * KS2 * 2);        // B area offset

    const int KT = K >> 6;

    // Prologue: tile 0 -> stage 0
#pragma unroll
    for (int p = 0; p < 4; ++p) {
        cpa16(s0 + oBase + p * rowStep,         Ag + (long)(p * 32) * K);
        cpa16(s0 + bHalf + oBase + p * rowStep, Bg + (long)(p * 32) * K);
    }
    CP_COMMIT();

    float acc[4][4][4];
#pragma unroll
    for (int i = 0; i < 4; ++i)
#pragma unroll
        for (int j = 0; j < 4; ++j)
#pragma unroll
            for (int k = 0; k < 4; ++k) acc[i][j][k] = 0.0f;

    // Fragment base offsets (bytes, relative to stage base) — R9-proven scheme
    const u32 aoff = (u32)(((wm * 64 + (lane & 15)) * KS2 + (lane >> 4) * 8) * 2);
    const u32 boff = bHalf + (u32)(((wn * 32 + (lane & 7)) * KS2 + ((lane >> 3) & 1) * 8) * 2);

    for (int kt = 0; kt < KT; ++kt) {
        CP_WAIT0();
        __syncthreads();
        const int st = kt & 1;

        if (kt + 1 < KT) {
            const long ko = (long)(kt + 1) * 64;
            const u32 sb = s0 + (u32)(st ^ 1) * (u32)DG_STG;
#pragma unroll
            for (int p = 0; p < 4; ++p) {
                cpa16(sb + oBase + p * rowStep,         Ag + (long)(p * 32) * K + ko);
                cpa16(sb + bHalf + oBase + p * rowStep, Bg + (long)(p * 32) * K + ko);
            }
        }
        CP_COMMIT();

        const u32 base = s0 + (u32)st * (u32)DG_STG;
        const u32 ab = base + aoff;
        const u32 bb = base + boff;
#pragma unroll
        for (int ks = 0; ks < 4; ++ks) {
            u32 a[4][4], b[4][2];
#pragma unroll
            for (int mi = 0; mi < 4; ++mi)
                ldsm_x4(a[mi][0], a[mi][1], a[mi][2], a[mi][3],
                        ab + (u32)((mi * 16 * KS2 + ks * 16) * 2));
#pragma unroll
            for (int ni = 0; ni < 4; ++ni)
                ldsm_x2(b[ni][0], b[ni][1],
                        bb + (u32)((ni * 8 * KS2 + ks * 16) * 2));
#pragma unroll
            for (int mi = 0; mi < 4; ++mi)
#pragma unroll
                for (int ni = 0; ni < 4; ++ni)
                    mma16816(acc[mi][ni], a[mi][0], a[mi][1], a[mi][2], a[mi][3],
                             b[ni][0], b[ni][1]);
        }
    }

    const int g = lane >> 2, tq = lane & 3;
#pragma unroll
    for (int mi = 0; mi < 4; ++mi) {
#pragma unroll
        for (int ni = 0; ni < 4; ++ni) {
            long row = m0 + wm * 64 + mi * 16 + g;
            long col = n0 + wn * 32 + ni * 8 + tq * 2;
            if (CF32) {
                float* C = (float*)Cp;
                *(float2*)(C + row * ldc + col)       = make_float2(acc[mi][ni][0], acc[mi][ni][1]);
                *(float2*)(C + (row + 8) * ldc + col) = make_float2(acc[mi][ni][2], acc[mi][ni][3]);
            } else {
                __half* C = (__half*)Cp;
                *(__half2*)(C + row * ldc + col)       = __floats2half2_rn(acc[mi][ni][0], acc[mi][ni][1]);
                *(__half2*)(C + (row + 8) * ldc + col) = __floats2half2_rn(acc[mi][ni][2], acc[mi][ni][3]);
            }
        }
    }
}

__global__ void __launch_bounds__(256, 2) k_qkv16()
{
    gemm128_body<false>(g_x16, g_wqkv16, g_qkv, D_, D3);
}
__global__ void __launch_bounds__(256, 2) k_proj16(float* __restrict__ out)
{
    gemm128_body<true>(g_ao, g_wproj16, out, D_, D_);
}

// ===========================================================================
// k_zsum: Z[k] = sum_q exp(scale * K[k]·Q[q])  — [R9 verbatim]
// ===========================================================================
__global__ void k_zsum()
{
    __shared__ __align__(16) __half sK[128 * LS];
    __shared__ __align__(16) __half sQ[2][64 * LS];

    const int kc = blockIdx.x, bh = blockIdx.y;
    const int b = bh >> 4, h = bh & 15;
    const int t = threadIdx.x;
    const int warp = t >> 5, lane = t & 31;
    const int r2 = t >> 2, c2 = (t & 3) * 8;

    const __half* Qg = g_qkv + (long)b * T_ * D3 + h * DH_;
    const u32 dQ = smem_u32(&sQ[0][r2 * LS + c2]);
    const u32 QSBY = (u32)sizeof(sQ[0]);

    {
        const __half* Qsrc = Qg + (long)r2 * D3;
        cpa16(dQ, Qsrc + c2);
        cpa16(dQ + 64, Qsrc + c2 + 32);
        CP_COMMIT();
    }

    {
        const __half* Kg = g_qkv + ((long)b * T_ + kc * 128) * D3 + D_ + h * DH_;
        const int r_ = t >> 3, c_ = (t & 7) * 8;
#pragma unroll
        for (int p = 0; p < 4; ++p) {
            int r = r_ + p * 32;
            *(uint4*)&sK[r * LS + c_] = *(const uint4*)(Kg + (long)r * D3 + c_);
        }
    }
    __syncthreads();

    u32 a[4][4];
    {
        const u32 abase = smem_u32(&sK[(warp * 16 + (lane & 15)) * LS + (lane >> 4) * 8]);
#pragma unroll
        for (int ks = 0; ks < 4; ++ks)
            ldsm_x4(a[ks][0], a[ks][1], a[ks][2], a[ks][3], abase + (u32)(ks * 16 * 2));
    }

    float zacc0 = 0.0f, zacc1 = 0.0f;
    const u32 bqbase = smem_u32(&sQ[0][(lane & 7) * LS + ((lane >> 3) & 1) * 8]);

    for (int qt = 0; qt < 16; ++qt) {
        const int st = qt & 1;
        CP_WAIT0();
        __syncthreads();

        if (qt + 1 < 16) {
            const __half* Qsrc = Qg + (long)((qt + 1) * 64 + r2) * D3;
            const u32 o = (u32)(st ^ 1) * QSBY;
            cpa16(dQ + o, Qsrc + c2);
            cpa16(dQ + o + 64, Qsrc + c2 + 32);
        }
        CP_COMMIT();

        float c[8][4];
#pragma unroll
        for (int ni = 0; ni < 8; ++ni)
#pragma unroll
            for (int j = 0; j < 4; ++j) c[ni][j] = 0.0f;

        const u32 bq0 = bqbase + (u32)st * QSBY;
#pragma unroll
        for (int ks = 0; ks < 4; ++ks) {
            u32 bq[8][2];
#pragma unroll
            for (int ni = 0; ni < 8; ++ni)
                ldsm_x2(bq[ni][0], bq[ni][1],
                        bq0 + (u32)((ni * 8 * LS + ks * 16) * 2));
#pragma unroll
            for (int ni = 0; ni < 8; ++ni)
                mma16816(c[ni], a[ks][0], a[ks][1], a[ks][2], a[ks][3],
                         bq[ni][0], bq[ni][1]);
        }

#pragma unroll
        for (int ni = 0; ni < 8; ++ni) {
            zacc0 += __expf(0.125f * c[ni][0]) + __expf(0.125f * c[ni][1]);
            zacc1 += __expf(0.125f * c[ni][2]) + __expf(0.125f * c[ni][3]);
        }
    }

    zacc0 += __shfl_xor_sync(0xffffffffu, zacc0, 1);
    zacc0 += __shfl_xor_sync(0xffffffffu, zacc0, 2);
    zacc1 += __shfl_xor_sync(0xffffffffu, zacc1, 1);
    zacc1 += __shfl_xor_sync(0xffffffffu, zacc1, 2);
    if ((lane & 3) == 0) {
        int krow = kc * 128 + warp * 16 + (lane >> 2);
        g_Z[(long)bh * T_ + krow]     = zacc0;
        g_Z[(long)bh * T_ + krow + 8] = zacc1;
    }
}

// ===========================================================================
// k_attn: out[q,d] = sum_k exp(scale*q·k)/Z[k] * V[k,d]   [R9 verbatim]
// ===========================================================================
__global__ void k_attn()
{
    __shared__ __align__(16) __half sP[128 * LS];
    __shared__ __align__(16) __half sK[2][64 * LS];
    __shared__ __align__(16) __half sV[2][64 * LS];
    __shared__ float sRZ[2][64];

    const int qt = blockIdx.x, bh = blockIdx.y;
    const int b = bh >> 4, h = bh & 15;
    const int t = threadIdx.x;
    const int warp = t >> 5, lane = t & 31;
    const int g = lane >> 2, tq = lane & 3;
    const int r2 = t >> 2, c2 = (t & 3) * 8;

    const __half* Kg = g_qkv + (long)b * T_ * D3 + D_ + h * DH_;
    const __half* Vg = g_qkv + (long)b * T_ * D3 + 2 * D_ + h * DH_;
    const float* Zp = g_Z + (long)bh * T_;

    const u32 dK = smem_u32(&sK[0][r2 * LS + c2]);
    const u32 dV = smem_u32(&sV[0][r2 * LS + c2]);
    const u32 CSBY = (u32)sizeof(sK[0]);

    {
        const __half* Ksrc = Kg + (long)r2 * D3;
        const __half* Vsrc = Vg + (long)r2 * D3;
        cpa16(dK, Ksrc + c2);      cpa16(dK + 64, Ksrc + c2 + 32);
        cpa16(dV, Vsrc + c2);      cpa16(dV + 64, Vsrc + c2 + 32);
        CP_COMMIT();
    }

    {
        const __half* Qg = g_qkv + ((long)b * T_ + qt * 128) * D3 + h * DH_;
        const int r_ = t >> 3, c_ = (t & 7) * 8;
#pragma unroll
        for (int p = 0; p < 4; ++p) {
            int r = r_ + p * 32;
            *(uint4*)&sP[r * LS + c_] = *(const uint4*)(Qg + (long)r * D3 + c_);
        }
    }
    __syncthreads();

    u32 aq[4][4];
    const u32 pbase = smem_u32(&sP[(warp * 16 + (lane & 15)) * LS + (lane >> 4) * 8]);
#pragma unroll
    for (int ks = 0; ks < 4; ++ks)
        ldsm_x4(aq[ks][0], aq[ks][1], aq[ks][2], aq[ks][3], pbase + (u32)(ks * 16 * 2));

    float o[8][4];
#pragma unroll
    for (int ni = 0; ni < 8; ++ni)
#pragma unroll
        for (int j = 0; j < 4; ++j) o[ni][j] = 0.0f;

    const u32 bkbase = smem_u32(&sK[0][(lane & 7) * LS + ((lane >> 3) & 1) * 8]);
    const u32 bvbase = smem_u32(&sV[0][(lane & 15) * LS]);

    for (int kc = 0; kc < 16; ++kc) {
        const int st = kc & 1;
        CP_WAIT0();
        if (t < 64) sRZ[st][t] = 1.0f / Zp[kc * 64 + t];
        __syncthreads();

        if (kc + 1 < 16) {
            const __half* Ksrc = Kg + (long)((kc + 1) * 64 + r2) * D3;
            const __half* Vsrc = Vg + (long)((kc + 1) * 64 + r2) * D3;
            const u32 oo = (u32)(st ^ 1) * CSBY;
            cpa16(dK + oo, Ksrc + c2);      cpa16(dK + oo + 64, Ksrc + c2 + 32);
            cpa16(dV + oo, Vsrc + c2);      cpa16(dV + oo + 64, Vsrc + c2 + 32);
        }
        CP_COMMIT();

        float c[8][4];
#pragma unroll
        for (int ni = 0; ni < 8; ++ni)
#pragma unroll
            for (int j = 0; j < 4; ++j) c[ni][j] = 0.0f;

        const u32 bk0 = bkbase + (u32)st * CSBY;
#pragma unroll
        for (int ks = 0; ks < 4; ++ks) {
            u32 bk[8][2];
#pragma unroll
            for (int ni = 0; ni < 8; ++ni)
                ldsm_x2(bk[ni][0], bk[ni][1],
                        bk0 + (u32)((ni * 8 * LS + ks * 16) * 2));
#pragma unroll
            for (int ni = 0; ni < 8; ++ni)
                mma16816(c[ni], aq[ks][0], aq[ks][1], aq[ks][2], aq[ks][3],
                         bk[ni][0], bk[ni][1]);
        }

#pragma unroll
        for (int ni = 0; ni < 8; ++ni) {
            int col = ni * 8 + tq * 2;
            float rz0 = sRZ[st][col], rz1 = sRZ[st][col + 1];
            __half2 p01 = __floats2half2_rn(__expf(0.125f * c[ni][0]) * rz0,
                                            __expf(0.125f * c[ni][1]) * rz1);
            __half2 p23 = __floats2half2_rn(__expf(0.125f * c[ni][2]) * rz0,
                                            __expf(0.125f * c[ni][3]) * rz1);
            *(__half2*)&sP[(warp * 16 + g) * LS + col]     = p01;
            *(__half2*)&sP[(warp * 16 + g + 8) * LS + col] = p23;
        }
        __syncthreads();

        const u32 bv0 = bvbase + (u32)st * CSBY;
#pragma unroll
        for (int ks = 0; ks < 4; ++ks) {
            u32 ap[4];
            ldsm_x4(ap[0], ap[1], ap[2], ap[3], pbase + (u32)(ks * 16 * 2));
            u32 bv[8][2];
#pragma unroll
            for (int nd = 0; nd < 8; ++nd)
                ldsm_x2t(bv[nd][0], bv[nd][1],
                         bv0 + (u32)((ks * 16 * LS + nd * 8) * 2));
#pragma unroll
            for (int nd = 0; nd < 8; ++nd)
                mma16816(o[nd], ap[0], ap[1], ap[2], ap[3], bv[nd][0], bv[nd][1]);
        }
        __syncthreads();
    }

    __half* Og = g_ao + ((long)b * T_ + qt * 128) * D_ + h * DH_;
#pragma unroll
    for (int nd = 0; nd < 8; ++nd) {
        int row = warp * 16 + g;
        int col = nd * 8 + tq * 2;
        *(__half2*)(Og + (long)row * D_ + col)       = __floats2half2_rn(o[nd][0], o[nd][1]);
        *(__half2*)(Og + (long)(row + 8) * D_ + col) = __floats2half2_rn(o[nd][2], o[nd][3]);
    }
}

// ---------------------------------------------------------------------------
extern "C" void kernel_launch(void* const* d_in, const int* in_sizes, int n_in,
                              void* d_out, int out_size)
{
    const float* x      = (const float*)d_in[0];   // [8,1024,1024]
    const float* w_qkv  = (const float*)d_in[1];   // [3072,1024]
    const float* w_proj = (const float*)d_in[2];   // [1024,1024]
    float* out = (float*)d_out;                    // [8,1024,1024]

    cudaFuncSetAttribute(k_qkv16,  cudaFuncAttributeMaxDynamicSharedMemorySize, DG_DSMEM);
    cudaFuncSetAttribute(k_proj16, cudaFuncAttributeMaxDynamicSharedMemorySize, DG_DSMEM);

    k_f2h_x    <<<(long)BT * D_ / 2048, 256>>>(x);
    k_f2h_wqkv <<<(long)D3 * D_ / 2048, 256>>>(w_qkv);
    k_f2h_wproj<<<(long)D_ * D_ / 2048, 256>>>(w_proj);

    k_qkv16 <<<dim3(D3 / 128, BT / 128), 256, DG_DSMEM>>>();
    k_zsum  <<<dim3(T_ / 128, B_ * H_), 256>>>();
    k_attn  <<<dim3(T_ / 128, B_ * H_), 256>>>();
    k_proj16<<<dim3(D_ / 128, BT / 128), 256, DG_DSMEM>>>(out);
}

// round 15
// speedup vs baseline: 1.1217x; 1.0103x over previous
#include <cuda_runtime.h>
#include <cuda_fp16.h>

// Problem constants
#define B_  8
#define T_  1024
#define D_  1024
#define H_  16
#define DH_ 64
#define BT  (B_*T_)        // 8192
#define D3  (3*D_)         // 3072

#define KS2 72             // dense gemm smem row stride (64 + 8 pad), halves
#define LS 72              // attention smem row stride (64 + 8 pad), halves

#define DG_STG (256 * KS2 * 2)      // 36864 bytes: one stage (128 A rows + 128 B rows)
#define DG_DSMEM (2 * DG_STG)       // 73728, 2-stage

typedef unsigned int u32;

// Scratch (__device__ globals — referenced ONLY from device code!)
static __device__ __half g_x16[(long)BT * D_];       // x fp16, 16MB
static __device__ __half g_wqkv16[(long)D3 * D_];    // W_qkv fp16, 6MB
static __device__ __half g_wproj16[(long)D_ * D_];   // W_proj fp16, 2MB
static __device__ __half g_qkv[(long)BT * D3];       // [t][3D] fp16, 48MB
static __device__ float  g_Z[(long)B_*H_*T_];        // softmax denominators
static __device__ __half g_ao[(long)BT * D_];        // [t][D] fp16, 16MB

// ---------------------------------------------------------------------------
// PTX helpers
// ---------------------------------------------------------------------------
__device__ __forceinline__ u32 smem_u32(const void* p) {
    return (u32)__cvta_generic_to_shared(p);
}
__device__ __forceinline__ void ldsm_x4(u32& r0, u32& r1, u32& r2, u32& r3, u32 a) {
    asm volatile("ldmatrix.sync.aligned.m8n8.x4.shared.b16 {%0,%1,%2,%3},[%4];"
                 : "=r"(r0), "=r"(r1), "=r"(r2), "=r"(r3) : "r"(a));
}
__device__ __forceinline__ void ldsm_x2(u32& r0, u32& r1, u32 a) {
    asm volatile("ldmatrix.sync.aligned.m8n8.x2.shared.b16 {%0,%1},[%2];"
                 : "=r"(r0), "=r"(r1) : "r"(a));
}
__device__ __forceinline__ void ldsm_x2t(u32& r0, u32& r1, u32 a) {
    asm volatile("ldmatrix.sync.aligned.m8n8.x2.trans.shared.b16 {%0,%1},[%2];"
                 : "=r"(r0), "=r"(r1) : "r"(a));
}
__device__ __forceinline__ void mma16816(float c[4],
                                         u32 a0, u32 a1, u32 a2, u32 a3,
                                         u32 b0, u32 b1) {
    asm volatile("mma.sync.aligned.m16n8k16.row.col.f32.f16.f16.f32 "
                 "{%0,%1,%2,%3},{%4,%5,%6,%7},{%8,%9},{%0,%1,%2,%3};"
                 : "+f"(c[0]), "+f"(c[1]), "+f"(c[2]), "+f"(c[3])
                 : "r"(a0), "r"(a1), "r"(a2), "r"(a3), "r"(b0), "r"(b1));
}
__device__ __forceinline__ void cpa16(u32 dst, const void* src) {
    asm volatile("cp.async.cg.shared.global [%0],[%1],16;" :: "r"(dst), "l"(src));
}
#define CP_COMMIT() asm volatile("cp.async.commit_group;")
#define CP_WAIT0()  asm volatile("cp.async.wait_group 0;")

// ---------------------------------------------------------------------------
// fp32 -> fp16 conversion (globals named in device code only)
// ---------------------------------------------------------------------------
__device__ __forceinline__ void f2h_body(const float* __restrict__ s, __half* __restrict__ d)
{
    long i = ((long)blockIdx.x * blockDim.x + threadIdx.x) * 8;
    float4 v0 = *(const float4*)(s + i);
    float4 v1 = *(const float4*)(s + i + 4);
    uint4 o;
    __half2* hp = (__half2*)&o;
    hp[0] = __floats2half2_rn(v0.x, v0.y);
    hp[1] = __floats2half2_rn(v0.z, v0.w);
    hp[2] = __floats2half2_rn(v1.x, v1.y);
    hp[3] = __floats2half2_rn(v1.z, v1.w);
    *(uint4*)(d + i) = o;
}
__global__ void k_f2h_x(const float* __restrict__ s)     { f2h_body(s, g_x16); }
__global__ void k_f2h_wqkv(const float* __restrict__ s)  { f2h_body(s, g_wqkv16); }
__global__ void k_f2h_wproj(const float* __restrict__ s) { f2h_body(s, g_wproj16); }

// ---------------------------------------------------------------------------
// Dense NT GEMM body (R13-proven): 128x128x64, 2-stage cp.async.
// ---------------------------------------------------------------------------
template<bool CF32>
__device__ __forceinline__ void gemm128_body(
    const __half* __restrict__ A, const __half* __restrict__ B, void* Cp,
    int K, long ldc)
{
    extern __shared__ __align__(16) char dsm[];
    const u32 s0 = smem_u32(dsm);

    const int t = threadIdx.x;
    const int warp = t >> 5, lane = t & 31;
    const int wm = warp >> 2, wn = warp & 3;
    const long m0 = (long)blockIdx.y * 128, n0 = (long)blockIdx.x * 128;

    const int lr = t >> 3;          // 0..31 (row within 32-row pass)
    const int lc = (t & 7) * 8;     // 0..56 halves (16B chunks)

    const __half* Ag = A + (m0 + lr) * (long)K + lc;
    const __half* Bg = B + (n0 + lr) * (long)K + lc;

    const u32 oBase = (u32)((lr * KS2 + lc) * 2);
    const u32 rowStep = (u32)(32 * KS2 * 2);       // 32 rows
    const u32 bHalf = (u32)(128 * KS2 * 2);        // B area offset

    const int KT = K >> 6;

#pragma unroll
    for (int p = 0; p < 4; ++p) {
        cpa16(s0 + oBase + p * rowStep,         Ag + (long)(p * 32) * K);
        cpa16(s0 + bHalf + oBase + p * rowStep, Bg + (long)(p * 32) * K);
    }
    CP_COMMIT();

    float acc[4][4][4];
#pragma unroll
    for (int i = 0; i < 4; ++i)
#pragma unroll
        for (int j = 0; j < 4; ++j)
#pragma unroll
            for (int k = 0; k < 4; ++k) acc[i][j][k] = 0.0f;

    const u32 aoff = (u32)(((wm * 64 + (lane & 15)) * KS2 + (lane >> 4) * 8) * 2);
    const u32 boff = bHalf + (u32)(((wn * 32 + (lane & 7)) * KS2 + ((lane >> 3) & 1) * 8) * 2);

    for (int kt = 0; kt < KT; ++kt) {
        CP_WAIT0();
        __syncthreads();
        const int st = kt & 1;

        if (kt + 1 < KT) {
            const long ko = (long)(kt + 1) * 64;
            const u32 sb = s0 + (u32)(st ^ 1) * (u32)DG_STG;
#pragma unroll
            for (int p = 0; p < 4; ++p) {
                cpa16(sb + oBase + p * rowStep,         Ag + (long)(p * 32) * K + ko);
                cpa16(sb + bHalf + oBase + p * rowStep, Bg + (long)(p * 32) * K + ko);
            }
        }
        CP_COMMIT();

        const u32 base = s0 + (u32)st * (u32)DG_STG;
        const u32 ab = base + aoff;
        const u32 bb = base + boff;
#pragma unroll
        for (int ks = 0; ks < 4; ++ks) {
            u32 a[4][4], b[4][2];
#pragma unroll
            for (int mi = 0; mi < 4; ++mi)
                ldsm_x4(a[mi][0], a[mi][1], a[mi][2], a[mi][3],
                        ab + (u32)((mi * 16 * KS2 + ks * 16) * 2));
#pragma unroll
            for (int ni = 0; ni < 4; ++ni)
                ldsm_x2(b[ni][0], b[ni][1],
                        bb + (u32)((ni * 8 * KS2 + ks * 16) * 2));
#pragma unroll
            for (int mi = 0; mi < 4; ++mi)
#pragma unroll
                for (int ni = 0; ni < 4; ++ni)
                    mma16816(acc[mi][ni], a[mi][0], a[mi][1], a[mi][2], a[mi][3],
                             b[ni][0], b[ni][1]);
        }
    }

    const int g = lane >> 2, tq = lane & 3;
#pragma unroll
    for (int mi = 0; mi < 4; ++mi) {
#pragma unroll
        for (int ni = 0; ni < 4; ++ni) {
            long row = m0 + wm * 64 + mi * 16 + g;
            long col = n0 + wn * 32 + ni * 8 + tq * 2;
            if (CF32) {
                float* C = (float*)Cp;
                *(float2*)(C + row * ldc + col)       = make_float2(acc[mi][ni][0], acc[mi][ni][1]);
                *(float2*)(C + (row + 8) * ldc + col) = make_float2(acc[mi][ni][2], acc[mi][ni][3]);
            } else {
                __half* C = (__half*)Cp;
                *(__half2*)(C + row * ldc + col)       = __floats2half2_rn(acc[mi][ni][0], acc[mi][ni][1]);
                *(__half2*)(C + (row + 8) * ldc + col) = __floats2half2_rn(acc[mi][ni][2], acc[mi][ni][3]);
            }
        }
    }
}

__global__ void __launch_bounds__(256, 2) k_qkv16()
{
    gemm128_body<false>(g_x16, g_wqkv16, g_qkv, D_, D3);
}
__global__ void __launch_bounds__(256, 2) k_proj16(float* __restrict__ out)
{
    gemm128_body<true>(g_ao, g_wproj16, out, D_, D_);
}

// ===========================================================================
// k_zsum: Z[k] = sum_q exp(scale * K[k]·Q[q])  — [R9/R13 verbatim]
// ===========================================================================
__global__ void k_zsum()
{
    __shared__ __align__(16) __half sK[128 * LS];
    __shared__ __align__(16) __half sQ[2][64 * LS];

    const int kc = blockIdx.x, bh = blockIdx.y;
    const int b = bh >> 4, h = bh & 15;
    const int t = threadIdx.x;
    const int warp = t >> 5, lane = t & 31;
    const int r2 = t >> 2, c2 = (t & 3) * 8;

    const __half* Qg = g_qkv + (long)b * T_ * D3 + h * DH_;
    const u32 dQ = smem_u32(&sQ[0][r2 * LS + c2]);
    const u32 QSBY = (u32)sizeof(sQ[0]);

    {
        const __half* Qsrc = Qg + (long)r2 * D3;
        cpa16(dQ, Qsrc + c2);
        cpa16(dQ + 64, Qsrc + c2 + 32);
        CP_COMMIT();
    }

    {
        const __half* Kg = g_qkv + ((long)b * T_ + kc * 128) * D3 + D_ + h * DH_;
        const int r_ = t >> 3, c_ = (t & 7) * 8;
#pragma unroll
        for (int p = 0; p < 4; ++p) {
            int r = r_ + p * 32;
            *(uint4*)&sK[r * LS + c_] = *(const uint4*)(Kg + (long)r * D3 + c_);
        }
    }
    __syncthreads();

    u32 a[4][4];
    {
        const u32 abase = smem_u32(&sK[(warp * 16 + (lane & 15)) * LS + (lane >> 4) * 8]);
#pragma unroll
        for (int ks = 0; ks < 4; ++ks)
            ldsm_x4(a[ks][0], a[ks][1], a[ks][2], a[ks][3], abase + (u32)(ks * 16 * 2));
    }

    float zacc0 = 0.0f, zacc1 = 0.0f;
    const u32 bqbase = smem_u32(&sQ[0][(lane & 7) * LS + ((lane >> 3) & 1) * 8]);

    for (int qt = 0; qt < 16; ++qt) {
        const int st = qt & 1;
        CP_WAIT0();
        __syncthreads();

        if (qt + 1 < 16) {
            const __half* Qsrc = Qg + (long)((qt + 1) * 64 + r2) * D3;
            const u32 o = (u32)(st ^ 1) * QSBY;
            cpa16(dQ + o, Qsrc + c2);
            cpa16(dQ + o + 64, Qsrc + c2 + 32);
        }
        CP_COMMIT();

        float c[8][4];
#pragma unroll
        for (int ni = 0; ni < 8; ++ni)
#pragma unroll
            for (int j = 0; j < 4; ++j) c[ni][j] = 0.0f;

        const u32 bq0 = bqbase + (u32)st * QSBY;
#pragma unroll
        for (int ks = 0; ks < 4; ++ks) {
            u32 bq[8][2];
#pragma unroll
            for (int ni = 0; ni < 8; ++ni)
                ldsm_x2(bq[ni][0], bq[ni][1],
                        bq0 + (u32)((ni * 8 * LS + ks * 16) * 2));
#pragma unroll
            for (int ni = 0; ni < 8; ++ni)
                mma16816(c[ni], a[ks][0], a[ks][1], a[ks][2], a[ks][3],
                         bq[ni][0], bq[ni][1]);
        }

#pragma unroll
        for (int ni = 0; ni < 8; ++ni) {
            zacc0 += __expf(0.125f * c[ni][0]) + __expf(0.125f * c[ni][1]);
            zacc1 += __expf(0.125f * c[ni][2]) + __expf(0.125f * c[ni][3]);
        }
    }

    zacc0 += __shfl_xor_sync(0xffffffffu, zacc0, 1);
    zacc0 += __shfl_xor_sync(0xffffffffu, zacc0, 2);
    zacc1 += __shfl_xor_sync(0xffffffffu, zacc1, 1);
    zacc1 += __shfl_xor_sync(0xffffffffu, zacc1, 2);
    if ((lane & 3) == 0) {
        int krow = kc * 128 + warp * 16 + (lane >> 2);
        g_Z[(long)bh * T_ + krow]     = zacc0;
        g_Z[(long)bh * T_ + krow + 8] = zacc1;
    }
}

// ===========================================================================
// k_attn: out[q,d] = sum_k exp(scale*q·k)/Z[k] * V[k,d]
// sP is warp-private (each warp writes/reads only its own 16 q-rows):
// only ONE cross-warp barrier per iteration (sK/sV/sRZ staging guard).
// ===========================================================================
__global__ void k_attn()
{
    __shared__ __align__(16) __half sP[128 * LS];
    __shared__ __align__(16) __half sK[2][64 * LS];
    __shared__ __align__(16) __half sV[2][64 * LS];
    __shared__ float sRZ[2][64];

    const int qt = blockIdx.x, bh = blockIdx.y;
    const int b = bh >> 4, h = bh & 15;
    const int t = threadIdx.x;
    const int warp = t >> 5, lane = t & 31;
    const int g = lane >> 2, tq = lane & 3;
    const int r2 = t >> 2, c2 = (t & 3) * 8;

    const __half* Kg = g_qkv + (long)b * T_ * D3 + D_ + h * DH_;
    const __half* Vg = g_qkv + (long)b * T_ * D3 + 2 * D_ + h * DH_;
    const float* Zp = g_Z + (long)bh * T_;

    const u32 dK = smem_u32(&sK[0][r2 * LS + c2]);
    const u32 dV = smem_u32(&sV[0][r2 * LS + c2]);
    const u32 CSBY = (u32)sizeof(sK[0]);

    {
        const __half* Ksrc = Kg + (long)r2 * D3;
        const __half* Vsrc = Vg + (long)r2 * D3;
        cpa16(dK, Ksrc + c2);      cpa16(dK + 64, Ksrc + c2 + 32);
        cpa16(dV, Vsrc + c2);      cpa16(dV + 64, Vsrc + c2 + 32);
        CP_COMMIT();
    }

    {
        const __half* Qg = g_qkv + ((long)b * T_ + qt * 128) * D3 + h * DH_;
        const int r_ = t >> 3, c_ = (t & 7) * 8;
#pragma unroll
        for (int p = 0; p < 4; ++p) {
            int r = r_ + p * 32;
            *(uint4*)&sP[r * LS + c_] = *(const uint4*)(Qg + (long)r * D3 + c_);
        }
    }
    __syncthreads();

    u32 aq[4][4];
    const u32 pbase = smem_u32(&sP[(warp * 16 + (lane & 15)) * LS + (lane >> 4) * 8]);
#pragma unroll
    for (int ks = 0; ks < 4; ++ks)
        ldsm_x4(aq[ks][0], aq[ks][1], aq[ks][2], aq[ks][3], pbase + (u32)(ks * 16 * 2));

    float o[8][4];
#pragma unroll
    for (int ni = 0; ni < 8; ++ni)
#pragma unroll
        for (int j = 0; j < 4; ++j) o[ni][j] = 0.0f;

    const u32 bkbase = smem_u32(&sK[0][(lane & 7) * LS + ((lane >> 3) & 1) * 8]);
    const u32 bvbase = smem_u32(&sV[0][(lane & 15) * LS]);

    for (int kc = 0; kc < 16; ++kc) {
        const int st = kc & 1;
        CP_WAIT0();
        if (t < 64) sRZ[st][t] = 1.0f / Zp[kc * 64 + t];
        __syncthreads();          // the ONLY cross-warp barrier per iteration

        if (kc + 1 < 16) {
            const __half* Ksrc = Kg + (long)((kc + 1) * 64 + r2) * D3;
            const __half* Vsrc = Vg + (long)((kc + 1) * 64 + r2) * D3;
            const u32 oo = (u32)(st ^ 1) * CSBY;
            cpa16(dK + oo, Ksrc + c2);      cpa16(dK + oo + 64, Ksrc + c2 + 32);
            cpa16(dV + oo, Vsrc + c2);      cpa16(dV + oo + 64, Vsrc + c2 + 32);
        }
        CP_COMMIT();

        float c[8][4];
#pragma unroll
        for (int ni = 0; ni < 8; ++ni)
#pragma unroll
            for (int j = 0; j < 4; ++j) c[ni][j] = 0.0f;

        const u32 bk0 = bkbase + (u32)st * CSBY;
#pragma unroll
        for (int ks = 0; ks < 4; ++ks) {
            u32 bk[8][2];
#pragma unroll
            for (int ni = 0; ni < 8; ++ni)
                ldsm_x2(bk[ni][0], bk[ni][1],
                        bk0 + (u32)((ni * 8 * LS + ks * 16) * 2));
#pragma unroll
            for (int ni = 0; ni < 8; ++ni)
                mma16816(c[ni], aq[ks][0], aq[ks][1], aq[ks][2], aq[ks][3],
                         bk[ni][0], bk[ni][1]);
        }

        // P write (warp-private rows of sP)
#pragma unroll
        for (int ni = 0; ni < 8; ++ni) {
            int col = ni * 8 + tq * 2;
            float rz0 = sRZ[st][col], rz1 = sRZ[st][col + 1];
            __half2 p01 = __floats2half2_rn(__expf(0.125f * c[ni][0]) * rz0,
                                            __expf(0.125f * c[ni][1]) * rz1);
            __half2 p23 = __floats2half2_rn(__expf(0.125f * c[ni][2]) * rz0,
                                            __expf(0.125f * c[ni][3]) * rz1);
            *(__half2*)&sP[(warp * 16 + g) * LS + col]     = p01;
            *(__half2*)&sP[(warp * 16 + g + 8) * LS + col] = p23;
        }
        __syncwarp();             // same-warp STS -> LDSM visibility

        const u32 bv0 = bvbase + (u32)st * CSBY;
#pragma unroll
        for (int ks = 0; ks < 4; ++ks) {
            u32 ap[4];
            ldsm_x4(ap[0], ap[1], ap[2], ap[3], pbase + (u32)(ks * 16 * 2));
            u32 bv[8][2];
#pragma unroll
            for (int nd = 0; nd < 8; ++nd)
                ldsm_x2t(bv[nd][0], bv[nd][1],
                         bv0 + (u32)((ks * 16 * LS + nd * 8) * 2));
#pragma unroll
            for (int nd = 0; nd < 8; ++nd)
                mma16816(o[nd], ap[0], ap[1], ap[2], ap[3], bv[nd][0], bv[nd][1]);
        }
        // no end-of-loop barrier: sP rows are warp-private; ldmatrix.sync
        // completes all lane reads before the next iteration's stores.
    }

    __half* Og = g_ao + ((long)b * T_ + qt * 128) * D_ + h * DH_;
#pragma unroll
    for (int nd = 0; nd < 8; ++nd) {
        int row = warp * 16 + g;
        int col = nd * 8 + tq * 2;
        *(__half2*)(Og + (long)row * D_ + col)       = __floats2half2_rn(o[nd][0], o[nd][1]);
        *(__half2*)(Og + (long)(row + 8) * D_ + col) = __floats2half2_rn(o[nd][2], o[nd][3]);
    }
}

// ---------------------------------------------------------------------------
extern "C" void kernel_launch(void* const* d_in, const int* in_sizes, int n_in,
                              void* d_out, int out_size)
{
    const float* x      = (const float*)d_in[0];   // [8,1024,1024]
    const float* w_qkv  = (const float*)d_in[1];   // [3072,1024]
    const float* w_proj = (const float*)d_in[2];   // [1024,1024]
    float* out = (float*)d_out;                    // [8,1024,1024]

    cudaFuncSetAttribute(k_qkv16,  cudaFuncAttributeMaxDynamicSharedMemorySize, DG_DSMEM);
    cudaFuncSetAttribute(k_proj16, cudaFuncAttributeMaxDynamicSharedMemorySize, DG_DSMEM);

    k_f2h_x    <<<(long)BT * D_ / 2048, 256>>>(x);
    k_f2h_wqkv <<<(long)D3 * D_ / 2048, 256>>>(w_qkv);
    k_f2h_wproj<<<(long)D_ * D_ / 2048, 256>>>(w_proj);

    k_qkv16 <<<dim3(D3 / 128, BT / 128), 256, DG_DSMEM>>>();
    k_zsum  <<<dim3(T_ / 128, B_ * H_), 256>>>();
    k_attn  <<<dim3(T_ / 128, B_ * H_), 256>>>();
    k_proj16<<<dim3(D_ / 128, BT / 128), 256, DG_DSMEM>>>(out);
}

// round 16
// speedup vs baseline: 1.2000x; 1.0698x over previous
#include <cuda_runtime.h>
#include <cuda_fp16.h>

// Problem constants
#define B_  8
#define T_  1024
#define D_  1024
#define H_  16
#define DH_ 64
#define BT  (B_*T_)        // 8192
#define D3  (3*D_)         // 3072

#define KS2 72             // dense gemm smem row stride (64 + 8 pad), halves
#define LS 72              // attention smem row stride (64 + 8 pad), halves

#define DG_STG (256 * KS2 * 2)      // 36864 bytes: one stage (128 A rows + 128 B rows)
#define DG_DSMEM (2 * DG_STG)       // 73728, 2-stage

typedef unsigned int u32;

// Scratch (__device__ globals — referenced ONLY from device code!)
static __device__ __half g_x16[(long)BT * D_];       // x fp16, 16MB
static __device__ __half g_wqkv16[(long)D3 * D_];    // W_qkv fp16, 6MB
static __device__ __half g_wproj16[(long)D_ * D_];   // W_proj fp16, 2MB
static __device__ __half g_qkv[(long)BT * D3];       // [t][3D] fp16, 48MB
static __device__ float  g_Z[(long)B_*H_*T_];        // softmax denominators
static __device__ __half g_ao[(long)BT * D_];        // [t][D] fp16, 16MB

// ---------------------------------------------------------------------------
// PTX helpers
// ---------------------------------------------------------------------------
__device__ __forceinline__ u32 smem_u32(const void* p) {
    return (u32)__cvta_generic_to_shared(p);
}
__device__ __forceinline__ void ldsm_x4(u32& r0, u32& r1, u32& r2, u32& r3, u32 a) {
    asm volatile("ldmatrix.sync.aligned.m8n8.x4.shared.b16 {%0,%1,%2,%3},[%4];"
                 : "=r"(r0), "=r"(r1), "=r"(r2), "=r"(r3) : "r"(a));
}
__device__ __forceinline__ void ldsm_x2(u32& r0, u32& r1, u32 a) {
    asm volatile("ldmatrix.sync.aligned.m8n8.x2.shared.b16 {%0,%1},[%2];"
                 : "=r"(r0), "=r"(r1) : "r"(a));
}
__device__ __forceinline__ void ldsm_x2t(u32& r0, u32& r1, u32 a) {
    asm volatile("ldmatrix.sync.aligned.m8n8.x2.trans.shared.b16 {%0,%1},[%2];"
                 : "=r"(r0), "=r"(r1) : "r"(a));
}
__device__ __forceinline__ void mma16816(float c[4],
                                         u32 a0, u32 a1, u32 a2, u32 a3,
                                         u32 b0, u32 b1) {
    asm volatile("mma.sync.aligned.m16n8k16.row.col.f32.f16.f16.f32 "
                 "{%0,%1,%2,%3},{%4,%5,%6,%7},{%8,%9},{%0,%1,%2,%3};"
                 : "+f"(c[0]), "+f"(c[1]), "+f"(c[2]), "+f"(c[3])
                 : "r"(a0), "r"(a1), "r"(a2), "r"(a3), "r"(b0), "r"(b1));
}
__device__ __forceinline__ void cpa16(u32 dst, const void* src) {
    asm volatile("cp.async.cg.shared.global [%0],[%1],16;" :: "r"(dst), "l"(src));
}
#define CP_COMMIT() asm volatile("cp.async.commit_group;")
#define CP_WAIT0()  asm volatile("cp.async.wait_group 0;")

__device__ __forceinline__ u32 h2u(__half2 h) { return *(u32*)&h; }

// ---------------------------------------------------------------------------
// fp32 -> fp16 conversion (globals named in device code only)
// ---------------------------------------------------------------------------
__device__ __forceinline__ void f2h_body(const float* __restrict__ s, __half* __restrict__ d)
{
    long i = ((long)blockIdx.x * blockDim.x + threadIdx.x) * 8;
    float4 v0 = *(const float4*)(s + i);
    float4 v1 = *(const float4*)(s + i + 4);
    uint4 o;
    __half2* hp = (__half2*)&o;
    hp[0] = __floats2half2_rn(v0.x, v0.y);
    hp[1] = __floats2half2_rn(v0.z, v0.w);
    hp[2] = __floats2half2_rn(v1.x, v1.y);
    hp[3] = __floats2half2_rn(v1.z, v1.w);
    *(uint4*)(d + i) = o;
}
__global__ void k_f2h_x(const float* __restrict__ s)     { f2h_body(s, g_x16); }
__global__ void k_f2h_wqkv(const float* __restrict__ s)  { f2h_body(s, g_wqkv16); }
__global__ void k_f2h_wproj(const float* __restrict__ s) { f2h_body(s, g_wproj16); }

// ---------------------------------------------------------------------------
// Dense NT GEMM body (R13-proven): 128x128x64, 2-stage cp.async.
// ---------------------------------------------------------------------------
template<bool CF32>
__device__ __forceinline__ void gemm128_body(
    const __half* __restrict__ A, const __half* __restrict__ B, void* Cp,
    int K, long ldc)
{
    extern __shared__ __align__(16) char dsm[];
    const u32 s0 = smem_u32(dsm);

    const int t = threadIdx.x;
    const int warp = t >> 5, lane = t & 31;
    const int wm = warp >> 2, wn = warp & 3;
    const long m0 = (long)blockIdx.y * 128, n0 = (long)blockIdx.x * 128;

    const int lr = t >> 3;          // 0..31 (row within 32-row pass)
    const int lc = (t & 7) * 8;     // 0..56 halves (16B chunks)

    const __half* Ag = A + (m0 + lr) * (long)K + lc;
    const __half* Bg = B + (n0 + lr) * (long)K + lc;

    const u32 oBase = (u32)((lr * KS2 + lc) * 2);
    const u32 rowStep = (u32)(32 * KS2 * 2);       // 32 rows
    const u32 bHalf = (u32)(128 * KS2 * 2);        // B area offset

    const int KT = K >> 6;

#pragma unroll
    for (int p = 0; p < 4; ++p) {
        cpa16(s0 + oBase + p * rowStep,         Ag + (long)(p * 32) * K);
        cpa16(s0 + bHalf + oBase + p * rowStep, Bg + (long)(p * 32) * K);
    }
    CP_COMMIT();

    float acc[4][4][4];
#pragma unroll
    for (int i = 0; i < 4; ++i)
#pragma unroll
        for (int j = 0; j < 4; ++j)
#pragma unroll
            for (int k = 0; k < 4; ++k) acc[i][j][k] = 0.0f;

    const u32 aoff = (u32)(((wm * 64 + (lane & 15)) * KS2 + (lane >> 4) * 8) * 2);
    const u32 boff = bHalf + (u32)(((wn * 32 + (lane & 7)) * KS2 + ((lane >> 3) & 1) * 8) * 2);

    for (int kt = 0; kt < KT; ++kt) {
        CP_WAIT0();
        __syncthreads();
        const int st = kt & 1;

        if (kt + 1 < KT) {
            const long ko = (long)(kt + 1) * 64;
            const u32 sb = s0 + (u32)(st ^ 1) * (u32)DG_STG;
#pragma unroll
            for (int p = 0; p < 4; ++p) {
                cpa16(sb + oBase + p * rowStep,         Ag + (long)(p * 32) * K + ko);
                cpa16(sb + bHalf + oBase + p * rowStep, Bg + (long)(p * 32) * K + ko);
            }
        }
        CP_COMMIT();

        const u32 base = s0 + (u32)st * (u32)DG_STG;
        const u32 ab = base + aoff;
        const u32 bb = base + boff;
#pragma unroll
        for (int ks = 0; ks < 4; ++ks) {
            u32 a[4][4], b[4][2];
#pragma unroll
            for (int mi = 0; mi < 4; ++mi)
                ldsm_x4(a[mi][0], a[mi][1], a[mi][2], a[mi][3],
                        ab + (u32)((mi * 16 * KS2 + ks * 16) * 2));
#pragma unroll
            for (int ni = 0; ni < 4; ++ni)
                ldsm_x2(b[ni][0], b[ni][1],
                        bb + (u32)((ni * 8 * KS2 + ks * 16) * 2));
#pragma unroll
            for (int mi = 0; mi < 4; ++mi)
#pragma unroll
                for (int ni = 0; ni < 4; ++ni)
                    mma16816(acc[mi][ni], a[mi][0], a[mi][1], a[mi][2], a[mi][3],
                             b[ni][0], b[ni][1]);
        }
    }

    const int g = lane >> 2, tq = lane & 3;
#pragma unroll
    for (int mi = 0; mi < 4; ++mi) {
#pragma unroll
        for (int ni = 0; ni < 4; ++ni) {
            long row = m0 + wm * 64 + mi * 16 + g;
            long col = n0 + wn * 32 + ni * 8 + tq * 2;
            if (CF32) {
                float* C = (float*)Cp;
                *(float2*)(C + row * ldc + col)       = make_float2(acc[mi][ni][0], acc[mi][ni][1]);
                *(float2*)(C + (row + 8) * ldc + col) = make_float2(acc[mi][ni][2], acc[mi][ni][3]);
            } else {
                __half* C = (__half*)Cp;
                *(__half2*)(C + row * ldc + col)       = __floats2half2_rn(acc[mi][ni][0], acc[mi][ni][1]);
                *(__half2*)(C + (row + 8) * ldc + col) = __floats2half2_rn(acc[mi][ni][2], acc[mi][ni][3]);
            }
        }
    }
}

__global__ void __launch_bounds__(256, 2) k_qkv16()
{
    gemm128_body<false>(g_x16, g_wqkv16, g_qkv, D_, D3);
}
__global__ void __launch_bounds__(256, 2) k_proj16(float* __restrict__ out)
{
    gemm128_body<true>(g_ao, g_wproj16, out, D_, D_);
}

// ===========================================================================
// k_zsum: Z[k] = sum_q exp(scale * K[k]·Q[q])  — [R9/R13 verbatim]
// ===========================================================================
__global__ void k_zsum()
{
    __shared__ __align__(16) __half sK[128 * LS];
    __shared__ __align__(16) __half sQ[2][64 * LS];

    const int kc = blockIdx.x, bh = blockIdx.y;
    const int b = bh >> 4, h = bh & 15;
    const int t = threadIdx.x;
    const int warp = t >> 5, lane = t & 31;
    const int r2 = t >> 2, c2 = (t & 3) * 8;

    const __half* Qg = g_qkv + (long)b * T_ * D3 + h * DH_;
    const u32 dQ = smem_u32(&sQ[0][r2 * LS + c2]);
    const u32 QSBY = (u32)sizeof(sQ[0]);

    {
        const __half* Qsrc = Qg + (long)r2 * D3;
        cpa16(dQ, Qsrc + c2);
        cpa16(dQ + 64, Qsrc + c2 + 32);
        CP_COMMIT();
    }

    {
        const __half* Kg = g_qkv + ((long)b * T_ + kc * 128) * D3 + D_ + h * DH_;
        const int r_ = t >> 3, c_ = (t & 7) * 8;
#pragma unroll
        for (int p = 0; p < 4; ++p) {
            int r = r_ + p * 32;
            *(uint4*)&sK[r * LS + c_] = *(const uint4*)(Kg + (long)r * D3 + c_);
        }
    }
    __syncthreads();

    u32 a[4][4];
    {
        const u32 abase = smem_u32(&sK[(warp * 16 + (lane & 15)) * LS + (lane >> 4) * 8]);
#pragma unroll
        for (int ks = 0; ks < 4; ++ks)
            ldsm_x4(a[ks][0], a[ks][1], a[ks][2], a[ks][3], abase + (u32)(ks * 16 * 2));
    }

    float zacc0 = 0.0f, zacc1 = 0.0f;
    const u32 bqbase = smem_u32(&sQ[0][(lane & 7) * LS + ((lane >> 3) & 1) * 8]);

    for (int qt = 0; qt < 16; ++qt) {
        const int st = qt & 1;
        CP_WAIT0();
        __syncthreads();

        if (qt + 1 < 16) {
            const __half* Qsrc = Qg + (long)((qt + 1) * 64 + r2) * D3;
            const u32 o = (u32)(st ^ 1) * QSBY;
            cpa16(dQ + o, Qsrc + c2);
            cpa16(dQ + o + 64, Qsrc + c2 + 32);
        }
        CP_COMMIT();

        float c[8][4];
#pragma unroll
        for (int ni = 0; ni < 8; ++ni)
#pragma unroll
            for (int j = 0; j < 4; ++j) c[ni][j] = 0.0f;

        const u32 bq0 = bqbase + (u32)st * QSBY;
#pragma unroll
        for (int ks = 0; ks < 4; ++ks) {
            u32 bq[8][2];
#pragma unroll
            for (int ni = 0; ni < 8; ++ni)
                ldsm_x2(bq[ni][0], bq[ni][1],
                        bq0 + (u32)((ni * 8 * LS + ks * 16) * 2));
#pragma unroll
            for (int ni = 0; ni < 8; ++ni)
                mma16816(c[ni], a[ks][0], a[ks][1], a[ks][2], a[ks][3],
                         bq[ni][0], bq[ni][1]);
        }

#pragma unroll
        for (int ni = 0; ni < 8; ++ni) {
            zacc0 += __expf(0.125f * c[ni][0]) + __expf(0.125f * c[ni][1]);
            zacc1 += __expf(0.125f * c[ni][2]) + __expf(0.125f * c[ni][3]);
        }
    }

    zacc0 += __shfl_xor_sync(0xffffffffu, zacc0, 1);
    zacc0 += __shfl_xor_sync(0xffffffffu, zacc0, 2);
    zacc1 += __shfl_xor_sync(0xffffffffu, zacc1, 1);
    zacc1 += __shfl_xor_sync(0xffffffffu, zacc1, 2);
    if ((lane & 3) == 0) {
        int krow = kc * 128 + warp * 16 + (lane >> 2);
        g_Z[(long)bh * T_ + krow]     = zacc0;
        g_Z[(long)bh * T_ + krow + 8] = zacc1;
    }
}

// ===========================================================================
// k_attn: out[q,d] = sum_k exp(scale*q·k)/Z[k] * V[k,d]
// P never touches smem: S-tile C-fragments are re-packed in registers into
// the A-fragments of the PV MMA (FlashAttention register trick).
// ===========================================================================
__global__ void k_attn()
{
    __shared__ __align__(16) __half sQst[128 * LS];   // Q staging only
    __shared__ __align__(16) __half sK[2][64 * LS];
    __shared__ __align__(16) __half sV[2][64 * LS];
    __shared__ float sRZ[2][64];

    const int qt = blockIdx.x, bh = blockIdx.y;
    const int b = bh >> 4, h = bh & 15;
    const int t = threadIdx.x;
    const int warp = t >> 5, lane = t & 31;
    const int g = lane >> 2, tq = lane & 3;
    const int r2 = t >> 2, c2 = (t & 3) * 8;

    const __half* Kg = g_qkv + (long)b * T_ * D3 + D_ + h * DH_;
    const __half* Vg = g_qkv + (long)b * T_ * D3 + 2 * D_ + h * DH_;
    const float* Zp = g_Z + (long)bh * T_;

    const u32 dK = smem_u32(&sK[0][r2 * LS + c2]);
    const u32 dV = smem_u32(&sV[0][r2 * LS + c2]);
    const u32 CSBY = (u32)sizeof(sK[0]);

    {
        const __half* Ksrc = Kg + (long)r2 * D3;
        const __half* Vsrc = Vg + (long)r2 * D3;
        cpa16(dK, Ksrc + c2);      cpa16(dK + 64, Ksrc + c2 + 32);
        cpa16(dV, Vsrc + c2);      cpa16(dV + 64, Vsrc + c2 + 32);
        CP_COMMIT();
    }

    {
        const __half* Qg = g_qkv + ((long)b * T_ + qt * 128) * D3 + h * DH_;
        const int r_ = t >> 3, c_ = (t & 7) * 8;
#pragma unroll
        for (int p = 0; p < 4; ++p) {
            int r = r_ + p * 32;
            *(uint4*)&sQst[r * LS + c_] = *(const uint4*)(Qg + (long)r * D3 + c_);
        }
    }
    __syncthreads();

    u32 aq[4][4];
    const u32 qbase = smem_u32(&sQst[(warp * 16 + (lane & 15)) * LS + (lane >> 4) * 8]);
#pragma unroll
    for (int ks = 0; ks < 4; ++ks)
        ldsm_x4(aq[ks][0], aq[ks][1], aq[ks][2], aq[ks][3], qbase + (u32)(ks * 16 * 2));

    float o[8][4];
#pragma unroll
    for (int ni = 0; ni < 8; ++ni)
#pragma unroll
        for (int j = 0; j < 4; ++j) o[ni][j] = 0.0f;

    const u32 bkbase = smem_u32(&sK[0][(lane & 7) * LS + ((lane >> 3) & 1) * 8]);
    const u32 bvbase = smem_u32(&sV[0][(lane & 15) * LS]);

    for (int kc = 0; kc < 16; ++kc) {
        const int st = kc & 1;
        CP_WAIT0();
        if (t < 64) sRZ[st][t] = 1.0f / Zp[kc * 64 + t];
        __syncthreads();          // the ONLY cross-warp barrier per iteration

        if (kc + 1 < 16) {
            const __half* Ksrc = Kg + (long)((kc + 1) * 64 + r2) * D3;
            const __half* Vsrc = Vg + (long)((kc + 1) * 64 + r2) * D3;
            const u32 oo = (u32)(st ^ 1) * CSBY;
            cpa16(dK + oo, Ksrc + c2);      cpa16(dK + oo + 64, Ksrc + c2 + 32);
            cpa16(dV + oo, Vsrc + c2);      cpa16(dV + oo + 64, Vsrc + c2 + 32);
        }
        CP_COMMIT();

        // S-phase: c[ni] covers S rows {g,g+8}+16*warp, cols ni*8+2tq..+1
        float c[8][4];
#pragma unroll
        for (int ni = 0; ni < 8; ++ni)
#pragma unroll
            for (int j = 0; j < 4; ++j) c[ni][j] = 0.0f;

        const u32 bk0 = bkbase + (u32)st * CSBY;
#pragma unroll
        for (int ks = 0; ks < 4; ++ks) {
            u32 bk[8][2];
#pragma unroll
            for (int ni = 0; ni < 8; ++ni)
                ldsm_x2(bk[ni][0], bk[ni][1],
                        bk0 + (u32)((ni * 8 * LS + ks * 16) * 2));
#pragma unroll
            for (int ni = 0; ni < 8; ++ni)
                mma16816(c[ni], aq[ks][0], aq[ks][1], aq[ks][2], aq[ks][3],
                         bk[ni][0], bk[ni][1]);
        }

        // p = exp(scale*s)/Z[k], packed DIRECTLY into PV A-fragments:
        // pf[ks] = { pack(c[2ks][0,1]), pack(c[2ks][2,3]),
        //            pack(c[2ks+1][0,1]), pack(c[2ks+1][2,3]) }
        u32 pf[4][4];
#pragma unroll
        for (int ni = 0; ni < 8; ++ni) {
            int col = ni * 8 + tq * 2;
            float rz0 = sRZ[st][col], rz1 = sRZ[st][col + 1];
            __half2 p01 = __floats2half2_rn(__expf(0.125f * c[ni][0]) * rz0,
                                            __expf(0.125f * c[ni][1]) * rz1);
            __half2 p23 = __floats2half2_rn(__expf(0.125f * c[ni][2]) * rz0,
                                            __expf(0.125f * c[ni][3]) * rz1);
            const int ks = ni >> 1;
            const int hi = (ni & 1) << 1;          // 0 or 2
            pf[ks][hi + 0] = h2u(p01);
            pf[ks][hi + 1] = h2u(p23);
        }

        // PV-phase: O += P·V (A from registers, B via ldmatrix.trans)
        const u32 bv0 = bvbase + (u32)st * CSBY;
#pragma unroll
        for (int ks = 0; ks < 4; ++ks) {
            u32 bv[8][2];
#pragma unroll
            for (int nd = 0; nd < 8; ++nd)
                ldsm_x2t(bv[nd][0], bv[nd][1],
                         bv0 + (u32)((ks * 16 * LS + nd * 8) * 2));
#pragma unroll
            for (int nd = 0; nd < 8; ++nd)
                mma16816(o[nd], pf[ks][0], pf[ks][1], pf[ks][2], pf[ks][3],
                         bv[nd][0], bv[nd][1]);
        }
    }

    __half* Og = g_ao + ((long)b * T_ + qt * 128) * D_ + h * DH_;
#pragma unroll
    for (int nd = 0; nd < 8; ++nd) {
        int row = warp * 16 + g;
        int col = nd * 8 + tq * 2;
        *(__half2*)(Og + (long)row * D_ + col)       = __floats2half2_rn(o[nd][0], o[nd][1]);
        *(__half2*)(Og + (long)(row + 8) * D_ + col) = __floats2half2_rn(o[nd][2], o[nd][3]);
    }
}

// ---------------------------------------------------------------------------
extern "C" void kernel_launch(void* const* d_in, const int* in_sizes, int n_in,
                              void* d_out, int out_size)
{
    const float* x      = (const float*)d_in[0];   // [8,1024,1024]
    const float* w_qkv  = (const float*)d_in[1];   // [3072,1024]
    const float* w_proj = (const float*)d_in[2];   // [1024,1024]
    float* out = (float*)d_out;                    // [8,1024,1024]

    cudaFuncSetAttribute(k_qkv16,  cudaFuncAttributeMaxDynamicSharedMemorySize, DG_DSMEM);
    cudaFuncSetAttribute(k_proj16, cudaFuncAttributeMaxDynamicSharedMemorySize, DG_DSMEM);

    k_f2h_x    <<<(long)BT * D_ / 2048, 256>>>(x);
    k_f2h_wqkv <<<(long)D3 * D_ / 2048, 256>>>(w_qkv);
    k_f2h_wproj<<<(long)D_ * D_ / 2048, 256>>>(w_proj);

    k_qkv16 <<<dim3(D3 / 128, BT / 128), 256, DG_DSMEM>>>();
    k_zsum  <<<dim3(T_ / 128, B_ * H_), 256>>>();
    k_attn  <<<dim3(T_ / 128, B_ * H_), 256>>>();
    k_proj16<<<dim3(D_ / 128, BT / 128), 256, DG_DSMEM>>>(out);
}